// round 10
// baseline (speedup 1.0000x reference)
#include <cuda_runtime.h>
#include <math.h>
#include <stdint.h>

#define N_PRED 65536
#define N_GT   128
#define N_CLS  256
#define MAX_DYN 10
#define GEPS   1e-6f
#define IOU_THRES 0.25f
#define CAND_C 128      // per-row LSA candidates: exactly the 128 smallest
#define SEL_CAP 4096    // collection buffer cap (smem)
#define GC_NEED 1408    // per-gt dynamic candidate depth (10 + 128 + 10*127)
#define NBMW   (N_PRED/32)   // 2048 bitmap words
#define LSA_CAP 16512        // smem LSA capacity; union <= 128*128 = 16384 <= LSA_CAP
#define LSA_DYN_BYTES (LSA_CAP*12 + LSA_CAP/8)  // 200208

typedef unsigned long long ull;

// ------------------- scratch (device globals; no runtime allocation) -------------------
__device__ float  d_giou[N_GT][N_PRED];   // 32MB  giou_T[g][p]
__device__ float  d_sig[N_PRED];          // 256KB sigmoid(cls[p][label]) per pred? no: per-(p) see k_cost
__device__ float  d_maxg[N_GT];
__device__ int    d_labels[N_GT];

__device__ int    d_ccand_idx[N_GT][CAND_C];  // orig col ids, sorted (cost,idx) asc
__device__ float  d_ccand_val[N_GT][CAND_C];
__device__ int    d_ccand_cnt[N_GT];
__device__ ull    d_ccpack[N_GT][CAND_C];     // (val_bits<<32)|compact_id, built in k_lsa

__device__ int    d_gcand_idx[N_GT][GC_NEED];
__device__ int    d_gcand_cnt[N_GT];

__device__ unsigned d_colbm[NBMW];
__device__ int    d_rev[N_PRED];          // compact id -> orig col
__device__ double d_v[N_PRED];            // column duals (compact-indexed)

// monotonic ascending key for float
__device__ __forceinline__ unsigned fkey(float f) {
    unsigned u = __float_as_uint(f);
    return (u & 0x80000000u) ? ~u : (u | 0x80000000u);
}

// cost recompute: must bit-match  __fadd_rn(-sig, __fmul_rn(-2, giou))
__device__ __forceinline__ float costv(float g, float sg) {
    return __fadd_rn(-sg, __fmul_rn(-2.0f, g));
}

// block bitonic sort, ascending, n = power of two >= blockDim
__device__ __forceinline__ void bsort(ull* a, int n, int tid, int nth) {
    for (int k = 2; k <= n; k <<= 1) {
        for (int j = k >> 1; j > 0; j >>= 1) {
            for (int i = tid; i < n; i += nth) {
                int ixj = i ^ j;
                if (ixj > i) {
                    bool up = ((i & k) == 0);
                    ull x = a[i], y = a[ixj];
                    if ((x > y) == up) { a[i] = y; a[ixj] = x; }
                }
            }
            __syncthreads();
        }
    }
}

// ------------------- labels decode + bitmap zero -------------------
__global__ void k_labels(const void* lab) {
    __shared__ int is32;
    if (threadIdx.x == 0) {
        const ull* p = (const ull*)lab;
        int f = 0;
        for (int i = 0; i < 64; i++) { if (p[i] >> 32) { f = 1; break; } }
        is32 = f;
    }
    __syncthreads();
    int t = threadIdx.x;
    if (t < N_GT) {
        long long v;
        if (is32) v = (long long)((const int*)lab)[t];
        else      v = ((const long long*)lab)[t];
        int iv = (int)v;
        if (iv < 0) iv = 0;
        if (iv >= N_CLS) iv = N_CLS - 1;
        d_labels[t] = iv;
    }
    for (int i = t; i < NBMW; i += blockDim.x) d_colbm[i] = 0u;
}

// ------------------- giou matrix + per-(pred,gt->label) sigmoid -------------
// NOTE: sigma depends only on (p, label[g]); but labels vary per g. To drop the cost
// matrix we need sig per (p,g) pair... however cost uses sig(cls[p][label[g]]).
// Observation: labels are few (<=128 distinct) but sig per (p,g) is 8.4M floats = too big.
// Instead d_sig here stores sig per (p, g) ONLY for the g actually used in select —
// not possible. So: store sig per (p, label-slot g) is the cost matrix itself.
// Resolution: select recomputes sig from cls on the fly? That re-reads 64MB of cls.
// Cheapest correct variant: keep a compact per-(g,p) SIG via recompute in select from
// d_giou and a per-(p,g) store is exactly the old cost matrix. Therefore we store
// sigc[g][p]? That's 32MB again. Final choice: keep storing the COST matrix after all,
// but ONLY its fkey-relevant form is needed... Simplest correct: store cost matrix.
// (see d_costm below)
__device__ float d_costm[N_GT][N_PRED];   // 32MB cost_T[g][p]

__global__ void k_cost(const float* __restrict__ pc, const float* __restrict__ ps,
                       const float* __restrict__ cls,
                       const float* __restrict__ gc, const float* __restrict__ gs) {
    __shared__ float glo0[N_GT], glo1[N_GT], glo2[N_GT];
    __shared__ float ghi0[N_GT], ghi1[N_GT], ghi2[N_GT];
    __shared__ float gvol[N_GT];
    __shared__ int   glab[N_GT];
    int tid = threadIdx.x;  // blockDim = 512
    if (tid < N_GT) {
        int t = tid;
        float c0 = gc[t*3+0], c1 = gc[t*3+1], c2 = gc[t*3+2];
        float s0 = gs[t*3+0], s1 = gs[t*3+1], s2 = gs[t*3+2];
        float h0s = __fmul_rn(s0, 0.5f), h1s = __fmul_rn(s1, 0.5f), h2s = __fmul_rn(s2, 0.5f);
        float l0 = __fsub_rn(c0, h0s), l1 = __fsub_rn(c1, h1s), l2 = __fsub_rn(c2, h2s);
        float h0 = __fadd_rn(c0, h0s), h1 = __fadd_rn(c1, h1s), h2 = __fadd_rn(c2, h2s);
        glo0[t]=l0; glo1[t]=l1; glo2[t]=l2; ghi0[t]=h0; ghi1[t]=h1; ghi2[t]=h2;
        gvol[t] = __fmul_rn(__fmul_rn(__fsub_rn(h0,l0), __fsub_rn(h1,l1)), __fsub_rn(h2,l2));
        glab[t] = d_labels[t];
    }
    __syncthreads();
    int p = blockIdx.x * 128 + (tid & 127);
    int gbase = (tid >> 7) * 32;          // 4 quarters of the g-loop
    float c0 = pc[p*3+0], c1 = pc[p*3+1], c2 = pc[p*3+2];
    float s0 = ps[p*3+0], s1 = ps[p*3+1], s2 = ps[p*3+2];
    float h0s = __fmul_rn(s0, 0.5f), h1s = __fmul_rn(s1, 0.5f), h2s = __fmul_rn(s2, 0.5f);
    float pl0 = __fsub_rn(c0, h0s), pl1 = __fsub_rn(c1, h1s), pl2 = __fsub_rn(c2, h2s);
    float ph0 = __fadd_rn(c0, h0s), ph1 = __fadd_rn(c1, h1s), ph2 = __fadd_rn(c2, h2s);
    float vol1 = __fmul_rn(__fmul_rn(__fsub_rn(ph0,pl0), __fsub_rn(ph1,pl1)), __fsub_rn(ph2,pl2));
    const float* clsrow = cls + (size_t)p * N_CLS;

    #pragma unroll 4
    for (int gi_ = 0; gi_ < 32; gi_++) {
        int g = gbase + gi_;
        float d0 = fmaxf(__fsub_rn(fminf(ph0, ghi0[g]), fmaxf(pl0, glo0[g])), 0.f);
        float d1 = fmaxf(__fsub_rn(fminf(ph1, ghi1[g]), fmaxf(pl1, glo1[g])), 0.f);
        float d2 = fmaxf(__fsub_rn(fminf(ph2, ghi2[g]), fmaxf(pl2, glo2[g])), 0.f);
        float ov = __fmul_rn(__fmul_rn(d0, d1), d2);
        float un = fmaxf(__fsub_rn(__fadd_rn(vol1, gvol[g]), ov), GEPS);
        float iou = __fdiv_rn(ov, un);
        float e0 = fmaxf(__fsub_rn(fmaxf(ph0, ghi0[g]), fminf(pl0, glo0[g])), 0.f);
        float e1 = fmaxf(__fsub_rn(fmaxf(ph1, ghi1[g]), fminf(pl1, glo1[g])), 0.f);
        float e2 = fmaxf(__fsub_rn(fmaxf(ph2, ghi2[g]), fminf(pl2, glo2[g])), 0.f);
        float enc = fmaxf(__fmul_rn(__fmul_rn(e0, e1), e2), GEPS);
        float gg = __fsub_rn(iou, __fdiv_rn(__fsub_rn(enc, un), enc));
        float cv = __ldg(clsrow + glab[g]);
        float sig = __fdiv_rn(1.0f, __fadd_rn(1.0f, expf(-cv)));
        d_giou[g][p] = gg;
        d_costm[g][p] = costv(gg, sig);
    }
}

// ------------------- selection: single-pass sample-threshold + sort -------------------
__global__ void k_select() {
    __shared__ ull buf[SEL_CAP];     // 32KB (aliased as hist in rare fallbacks)
    __shared__ ull samp[512];
    __shared__ float redf[512];
    __shared__ int s_cnt, s_c;

    int b = blockIdx.x, tid = threadIdx.x, nth = blockDim.x;  // nth = 512
    unsigned* hist = (unsigned*)buf;   // 2048-bin fallback histogram

    if (b < N_GT) {
        // ================= cost row =================
        int row = b;
        const float* crow = d_costm[row];
        if (tid < 512) {
            float v = crow[tid * 128];
            samp[tid] = ((ull)fkey(v) << 32) | (unsigned)(tid * 128);
        }
        __syncthreads();
        bsort(samp, 512, tid, nth);

        const int slist[5] = {4, 16, 64, 255, 511};
        int si = 0, cc = 0, truecnt = 0;
        while (true) {
            if (tid == 0) s_cnt = 0;
            __syncthreads();
            unsigned Tkey = (unsigned)(samp[slist[si]] >> 32);
            for (int j = tid; j < N_PRED; j += nth) {
                unsigned k = fkey(crow[j]);
                if (k <= Tkey) {
                    int slot = atomicAdd(&s_cnt, 1);
                    if (slot < SEL_CAP) buf[slot] = ((ull)k << 32) | (unsigned)j;
                }
            }
            __syncthreads();
            truecnt = s_cnt;
            cc = (truecnt < SEL_CAP) ? truecnt : SEL_CAP;
            if (truecnt >= CAND_C && truecnt <= SEL_CAP) break;
            if (truecnt > SEL_CAP) {
                for (int i = tid; i < 2048; i += nth) hist[i] = 0;
                __syncthreads();
                for (int j = tid; j < N_PRED; j += nth)
                    atomicAdd(&hist[fkey(crow[j]) >> 21], 1u);
                __syncthreads();
                if (tid == 0) {
                    unsigned need = CAND_C, cum = 0; int bb = 0;
                    for (; bb < 2047; bb++) { if (cum + hist[bb] >= need) break; cum += hist[bb]; }
                    s_c = bb; s_cnt = (int)(need - cum);
                }
                __syncthreads();
                unsigned pfx11 = (unsigned)s_c; int need1 = s_cnt;
                __syncthreads();
                for (int i = tid; i < 2048; i += nth) hist[i] = 0;
                __syncthreads();
                for (int j = tid; j < N_PRED; j += nth) {
                    unsigned k = fkey(crow[j]);
                    if ((k >> 21) == pfx11) atomicAdd(&hist[(k >> 10) & 2047u], 1u);
                }
                __syncthreads();
                if (tid == 0) {
                    unsigned need = (unsigned)need1, cum = 0; int bb = 0;
                    for (; bb < 2047; bb++) { if (cum + hist[bb] >= need) break; cum += hist[bb]; }
                    s_c = (int)((pfx11 << 11) | (unsigned)bb);
                    s_cnt = 0;
                }
                __syncthreads();
                unsigned pfx22 = (unsigned)s_c;
                __syncthreads();
                for (int j = tid; j < N_PRED; j += nth) {
                    unsigned k = fkey(crow[j]);
                    if ((k >> 10) <= pfx22) {
                        int slot = atomicAdd(&s_cnt, 1);
                        if (slot < SEL_CAP) buf[slot] = ((ull)k << 32) | (unsigned)j;
                    }
                }
                __syncthreads();
                truecnt = s_cnt;
                cc = (truecnt < SEL_CAP) ? truecnt : SEL_CAP;
                break;
            }
            si++;
            if (si >= 5) break;
            __syncthreads();
        }
        int n2 = 512; while (n2 < cc) n2 <<= 1;
        for (int i = tid + cc; i < n2; i += nth) buf[i] = 0xFFFFFFFFFFFFFFFFull;
        __syncthreads();
        bsort(buf, n2, tid, nth);
        int keep = (cc < CAND_C) ? cc : CAND_C;
        for (int i = tid; i < keep; i += nth) {
            ull e = buf[i];
            int j = (int)(e & 0xFFFFFFFFull);
            d_ccand_idx[row][i] = j;
            d_ccand_val[row][i] = crow[j];
            atomicOr(&d_colbm[j >> 5], 1u << (j & 31));
        }
        if (tid == 0) d_ccand_cnt[row] = keep;
    } else {
        // ================= giou row: fused max + collect =================
        int row = b - N_GT;
        const float* grow = d_giou[row];
        if (tid == 0) s_cnt = 0;
        __syncthreads();
        float lmax = -1e30f;
        for (int j = tid; j < N_PRED; j += nth) {
            float g = grow[j];
            lmax = fmaxf(lmax, g);
            if (g > IOU_THRES) {
                int slot = atomicAdd(&s_cnt, 1);
                if (slot < SEL_CAP) buf[slot] = ((ull)(~fkey(g)) << 32) | (unsigned)j;
            }
        }
        redf[tid] = lmax;
        __syncthreads();
        for (int off = nth >> 1; off > 0; off >>= 1) {
            if (tid < off) redf[tid] = fmaxf(redf[tid], redf[tid + off]);
            __syncthreads();
        }
        if (tid == 0) d_maxg[row] = redf[0];
        int tot = s_cnt;
        __syncthreads();
        if (tot > SEL_CAP) {
            for (int i = tid; i < 2048; i += nth) hist[i] = 0;
            __syncthreads();
            for (int j = tid; j < N_PRED; j += nth) {
                float g = grow[j];
                if (g > IOU_THRES) atomicAdd(&hist[(~fkey(g)) >> 21], 1u);
            }
            __syncthreads();
            if (tid == 0) {
                unsigned need = GC_NEED, cum = 0; int bb = 0;
                for (; bb < 2047; bb++) { if (cum + hist[bb] >= need) break; cum += hist[bb]; }
                s_c = bb; s_cnt = (int)(need - cum);
            }
            __syncthreads();
            unsigned pfx11 = (unsigned)s_c; int need1 = s_cnt;
            __syncthreads();
            for (int i = tid; i < 2048; i += nth) hist[i] = 0;
            __syncthreads();
            for (int j = tid; j < N_PRED; j += nth) {
                float g = grow[j];
                if (g > IOU_THRES) {
                    unsigned k = ~fkey(g);
                    if ((k >> 21) == pfx11) atomicAdd(&hist[(k >> 10) & 2047u], 1u);
                }
            }
            __syncthreads();
            if (tid == 0) {
                unsigned need = (unsigned)need1, cum = 0; int bb = 0;
                for (; bb < 2047; bb++) { if (cum + hist[bb] >= need) break; cum += hist[bb]; }
                s_c = (int)((pfx11 << 11) | (unsigned)bb);
                s_cnt = 0;
            }
            __syncthreads();
            unsigned pfx22 = (unsigned)s_c;
            __syncthreads();
            for (int j = tid; j < N_PRED; j += nth) {
                float g = grow[j];
                if (!(g > IOU_THRES)) continue;
                unsigned k = ~fkey(g);
                if ((k >> 10) <= pfx22) {
                    int slot = atomicAdd(&s_cnt, 1);
                    if (slot < SEL_CAP) buf[slot] = ((ull)k << 32) | (unsigned)j;
                }
            }
            __syncthreads();
            tot = s_cnt;
        }
        int cc = (tot < SEL_CAP) ? tot : SEL_CAP;
        int n2 = 512; while (n2 < cc) n2 <<= 1;
        for (int i = tid + cc; i < n2; i += nth) buf[i] = 0xFFFFFFFFFFFFFFFFull;
        __syncthreads();
        bsort(buf, n2, tid, nth);   // key asc == giou desc, idx asc
        int cnt = (cc < GC_NEED) ? cc : GC_NEED;
        for (int i = tid; i < cnt; i += nth)
            d_gcand_idx[row][i] = (int)(buf[i] & 0xFFFFFFFFull);
        if (tid == 0) d_gcand_cnt[row] = cnt;
    }
}

// ------------------- LSA (compact+remap+greedy+warp-sync augment) + dyn + output -----
__global__ void k_lsa(float* __restrict__ out) {
    extern __shared__ unsigned char dsm[];
    double*   shS  = (double*)dsm;                         // [LSA_CAP] shortest
    uint16_t* shT  = (uint16_t*)(dsm + (size_t)LSA_CAP*8); // [LSA_CAP] touched list
    uint8_t*  shP  = dsm + (size_t)LSA_CAP*10;             // [LSA_CAP] path (row)
    uint8_t*  shR  = dsm + (size_t)LSA_CAP*11;             // [LSA_CAP] row4col (255=free)
    unsigned* shSC = (unsigned*)(dsm + (size_t)LSA_CAP*12);// [LSA_CAP/32] SC bitmap
    int*      cbase = (int*)shT;                            // alias: dead before augment

    __shared__ double u[N_GT];
    __shared__ int SR[N_GT];
    __shared__ int c4r[N_GT];
    __shared__ int pend[N_GT];
    __shared__ int scnt[N_GT];
    __shared__ float s0val[N_GT];
    __shared__ int   s0idx[N_GT];
    __shared__ int   colro[N_GT];
    __shared__ int tsum[256];
    __shared__ int s_nT, s_npend;

    int tid = threadIdx.x, nth = blockDim.x;  // 256
    int lane = tid & 31;
    const double DINF = 1e300;

    // ---- compact scan of column bitmap ----
    int wbase = tid * 8;
    int cnts8[8]; int ssum = 0;
    #pragma unroll
    for (int w = 0; w < 8; w++) { cnts8[w] = __popc(d_colbm[wbase + w]); ssum += cnts8[w]; }
    tsum[tid] = ssum;
    __syncthreads();
    for (int off = 1; off < 256; off <<= 1) {
        int v_ = 0;
        if (tid >= off) v_ = tsum[tid - off];
        __syncthreads();
        tsum[tid] += v_;
        __syncthreads();
    }
    int excl = tsum[tid] - ssum;
    #pragma unroll
    for (int w = 0; w < 8; w++) { cbase[wbase + w] = excl; excl += cnts8[w]; }
    __syncthreads();
    int nK = tsum[255];
    if (nK > LSA_CAP) nK = LSA_CAP;   // impossible (union <= 16384), safety only

    // ---- remap: build packed (val|cid) candidate array + reverse map; zero duals ----
    for (int x = tid; x < N_GT * CAND_C; x += nth) {
        int row = x >> 7, s = x & 127;
        if (s < d_ccand_cnt[row]) {
            int j = d_ccand_idx[row][s];
            int w = j >> 5;
            int cid = cbase[w] + __popc(d_colbm[w] & ((1u << (j & 31)) - 1u));
            float v_ = d_ccand_val[row][s];
            d_ccpack[row][s] = ((ull)__float_as_uint(v_) << 32) | (unsigned)cid;
            d_rev[cid] = j;
        }
    }
    for (int i = tid; i < nK; i += nth) d_v[i] = 0.0;
    __syncthreads();   // cbase (shT alias) dead after this

    // ---- parallel prefetch of slot-0 data ----
    if (tid < N_GT) {
        scnt[tid] = d_ccand_cnt[tid];
        ull pk = d_ccpack[tid][0];
        s0idx[tid] = (int)(pk & 0xFFFFFFFFull);
        s0val[tid] = __uint_as_float((unsigned)(pk >> 32));
    }
    // ---- init smem LSA state ----
    for (int i = tid; i < nK; i += nth) shS[i] = DINF;
    for (int i = tid; i < nK; i += nth) shR[i] = 0xFF;
    for (int i = tid; i < (nK + 31) / 32; i += nth) shSC[i] = 0;
    if (tid < N_GT) c4r[tid] = -1;
    __syncthreads();

    // ---- greedy tight assignment (pure smem, serial) ----
    if (tid == 0) {
        s_npend = 0;
        for (int i = 0; i < N_GT; i++) {
            if (scnt[i] > 0) {
                u[i] = (double)s0val[i];
                int j = s0idx[i];
                if (j >= 0 && j < nK && shR[j] == 0xFF) {
                    shR[j] = (uint8_t)i; c4r[i] = j;
                    continue;
                }
            } else u[i] = 0.0;
            pend[s_npend++] = i;
        }
    }
    __syncthreads();

    // ---- warp-synchronous shortest augmenting path (warp 0 only) ----
    if (tid < 32) {
        int npend = s_npend;
        for (int pi = 0; pi < npend; pi++) {
            int cur = pend[pi];
            int row = cur, sink = -1, nSR = 0;
            double minval = 0.0;
            if (lane == 0) s_nT = 0;
            __syncwarp();
            for (int step = 0; step < N_GT; step++) {
                if (lane == 0) SR[nSR] = row;
                nSR++;
                double mv0 = minval, ui = u[row];
                int cnt = scnt[row];
                for (int s = lane; s < cnt; s += 32) {
                    ull pk = d_ccpack[row][s];
                    int jc = (int)(pk & 0xFFFFFFFFull);
                    if ((shSC[jc >> 5] >> (jc & 31)) & 1u) continue;
                    double r = ((mv0 + (double)__uint_as_float((unsigned)(pk >> 32))) - ui) - d_v[jc];
                    double old = shS[jc];
                    if (r < old) {
                        if (old == DINF) { int t2 = atomicAdd(&s_nT, 1); shT[t2] = (uint16_t)jc; }
                        shS[jc] = r; shP[jc] = (uint8_t)row;
                    }
                }
                __syncwarp();
                int nT = s_nT;
                double bv = DINF; int bj = 0x7fffffff;
                for (int t2 = lane; t2 < nT; t2 += 32) {
                    int jc = shT[t2];
                    if ((shSC[jc >> 5] >> (jc & 31)) & 1u) continue;
                    double sv = shS[jc];
                    if (sv < bv || (sv == bv && jc < bj)) { bv = sv; bj = jc; }
                }
                #pragma unroll
                for (int off = 16; off > 0; off >>= 1) {
                    double ov = __shfl_down_sync(0xffffffffu, bv, off);
                    int   oj = __shfl_down_sync(0xffffffffu, bj, off);
                    if (ov < bv || (ov == bv && oj < bj)) { bv = ov; bj = oj; }
                }
                bv = __shfl_sync(0xffffffffu, bv, 0);
                bj = __shfl_sync(0xffffffffu, bj, 0);
                if (bj < 0 || bj >= nK) { sink = -2; break; }
                minval = bv;
                if (lane == 0) shSC[bj >> 5] |= (1u << (bj & 31));
                __syncwarp();
                int r4 = shR[bj];
                if (r4 == 0xFF) { sink = bj; break; }
                row = r4;
            }
            if (sink >= 0) {
                if (lane == 0) {
                    u[cur] += minval;
                    for (int k = 1; k < nSR; k++) {
                        int i2 = SR[k];
                        u[i2] += minval - shS[c4r[i2]];
                    }
                }
                int nT = s_nT;
                for (int t2 = lane; t2 < nT; t2 += 32) {
                    int jc = shT[t2];
                    if ((shSC[jc >> 5] >> (jc & 31)) & 1u) d_v[jc] -= minval - shS[jc];
                }
                __syncwarp();
                if (lane == 0) {
                    int j = sink;
                    for (int it = 0; it <= N_GT && j >= 0; it++) {
                        int i2 = shP[j];
                        shR[j] = (uint8_t)i2;
                        int tmp = c4r[i2];
                        c4r[i2] = j;
                        j = tmp;
                        if (i2 == cur) break;
                    }
                }
                __syncwarp();
            }
            // reset touched + SC
            int nT = s_nT;
            for (int t2 = lane; t2 < nT; t2 += 32) shS[shT[t2]] = DINF;
            for (int i = lane; i < (nK + 31) / 32; i += 32) shSC[i] = 0;
            __syncwarp();
        }
    }
    __syncthreads();
    if (tid < N_GT) colro[tid] = (c4r[tid] >= 0) ? d_rev[c4r[tid]] : -1;
    __syncthreads();

    // ================= dynamic assignment phase (reuses dead dsm region) =================
    unsigned* used = (unsigned*)dsm;                    // 8KB @ 0
    int* res_p = (int*)(dsm + 8192);                    // 5632B
    int* res_g = (int*)(dsm + 13824);                   // 5632B
    int* pref  = (int*)(dsm + 19456);                   // 64KB: pref[g*128+s], depth 128
    int* gcnts = (int*)(dsm + 84992);                   // 512B
    int* ordv  = (int*)(dsm + 85504);                   // 512B
    float* mg  = (float*)(dsm + 86016);                 // 512B

    for (int i = tid; i < NBMW; i += nth) used[i] = 0;
    if (tid < N_GT) { gcnts[tid] = d_gcand_cnt[tid]; mg[tid] = d_maxg[tid]; }
    __syncthreads();
    // stable ascending argsort of maxg
    if (tid < N_GT) {
        float mv = mg[tid]; int r = 0;
        for (int j = 0; j < N_GT; j++) {
            float o = mg[j];
            if (o < mv || (o == mv && j < tid)) r++;
        }
        ordv[r] = tid;
    }
    for (int i = tid; i < N_GT * 128; i += nth) {
        int g = i >> 7, s = i & 127;
        pref[i] = (s < gcnts[g]) ? d_gcand_idx[g][s] : -1;
    }
    if (tid < N_GT) {
        int p = colro[tid];
        if (p >= 0 && p < N_PRED) atomicOr(&used[p >> 5], 1u << (p & 31));
        res_p[tid] = p;
        res_g[tid] = tid;
    }
    __syncthreads();
    if (tid < 32) {
        for (int t = 0; t < N_GT; t++) {
            int g = ordv[t];
            int cnt = gcnts[g];
            int picked = 0;
            for (int base = 0; base < cnt && picked < MAX_DYN; base += 32) {
                int idx = -1;
                if (base + lane < cnt)
                    idx = (base + lane < 128) ? pref[g * 128 + base + lane]
                                              : d_gcand_idx[g][base + lane];
                bool elig = (idx >= 0) && (idx < N_PRED) && !((used[idx >> 5] >> (idx & 31)) & 1u);
                unsigned m = __ballot_sync(0xffffffffu, elig);
                int K = MAX_DYN - picked;
                int pre = __popc(m & ((1u << lane) - 1u));
                if (elig && pre < K) {
                    atomicOr(&used[idx >> 5], 1u << (idx & 31));
                    res_p[128 + t * MAX_DYN + picked + pre] = idx;
                    res_g[128 + t * MAX_DYN + picked + pre] = g;
                }
                int got = __popc(m); if (got > K) got = K;
                picked += got;
                __syncwarp();
            }
            if (lane >= picked && lane < MAX_DYN) {
                res_p[128 + t * MAX_DYN + lane] = -1;
                res_g[128 + t * MAX_DYN + lane] = -1;
            }
            __syncwarp();
        }
    }
    __syncthreads();
    for (int i = tid; i < 1408; i += nth) {
        out[i]        = (float)res_p[i];
        out[1408 + i] = (float)res_g[i];
    }
}

// ------------------- launch (inputs resolved by element count) -------------------
extern "C" void kernel_launch(void* const* d_in, const int* in_sizes, int n_in,
                              void* d_out, int out_size) {
    const float* all_centers = 0;
    const float* all_sizes   = 0;
    const float* all_cls     = 0;
    const float* gt_centers  = 0;
    const float* gt_sizes    = 0;
    const void*  gt_labels   = 0;
    int seen196 = 0, seen384 = 0;
    for (int i = 0; i < n_in; i++) {
        long long s = in_sizes[i];
        if (s == (long long)N_PRED * N_CLS) {
            all_cls = (const float*)d_in[i];
        } else if (s == (long long)N_PRED * 3) {
            if (seen196++ == 0) all_centers = (const float*)d_in[i];
            else                all_sizes   = (const float*)d_in[i];
        } else if (s == (long long)N_GT * 3) {
            if (seen384++ == 0) gt_centers = (const float*)d_in[i];
            else                gt_sizes   = (const float*)d_in[i];
        } else if (s == (long long)N_GT) {
            gt_labels = d_in[i];
        }
    }

    cudaFuncSetAttribute(k_lsa, cudaFuncAttributeMaxDynamicSharedMemorySize, LSA_DYN_BYTES);

    k_labels<<<1, 128>>>(gt_labels);
    k_cost<<<N_PRED / 128, 512>>>(all_centers, all_sizes, all_cls, gt_centers, gt_sizes);
    k_select<<<2 * N_GT, 512>>>();
    k_lsa<<<1, 256, LSA_DYN_BYTES>>>((float*)d_out);
}

// round 11
// speedup vs baseline: 1.1518x; 1.1518x over previous
#include <cuda_runtime.h>
#include <math.h>
#include <stdint.h>

#define N_PRED 65536
#define N_GT   128
#define N_CLS  256
#define MAX_DYN 10
#define GEPS   1e-6f
#define IOU_THRES 0.25f
#define CAND_C 128      // per-row LSA candidates: exactly the 128 smallest
#define SEL_CAP 4096    // collection buffer cap (smem)
#define GC_NEED 1408    // per-gt dynamic candidate depth (10 + 128 + 10*127)
#define NBMW   (N_PRED/32)   // 2048 bitmap words
#define LSA_CAP 16512        // compact column universe cap; union <= 16384
#define SLOT_CAP 8192        // touched-column slots per augmentation
#define VV_CAP   2048        // nonzero-dual slots (persistent)

// dynamic smem layout for k_lsa
#define OFF_SLOT   0                         // u16[LSA_CAP]          33024
#define OFF_DIST   33024                     // f64[SLOT_CAP]         65536
#define OFF_PATH   98560                     // u8[SLOT_CAP]           8192
#define OFF_COL    106752                    // u16[SLOT_CAP]         16384
#define OFF_SC     123136                    // u32[SLOT_CAP/32]       1024
#define OFF_R      124160                    // u8[LSA_CAP]           16512
#define OFF_VSLOT  140672                    // u16[LSA_CAP]          33024
#define OFF_VVAL   173696                    // f64[VV_CAP]           16384
#define LSA_DYN_BYTES 190080

typedef unsigned long long ull;

// ------------------- scratch (device globals; no runtime allocation) -------------------
__device__ float  d_giou[N_GT][N_PRED];   // 32MB  giou_T[g][p]
__device__ float  d_costm[N_GT][N_PRED];  // 32MB  cost_T[g][p]
__device__ float  d_maxg[N_GT];

__device__ int    d_ccand_idx[N_GT][CAND_C];  // orig col ids, sorted (cost,idx) asc
__device__ float  d_ccand_val[N_GT][CAND_C];
__device__ int    d_ccand_cnt[N_GT];
__device__ ull    d_ccpack[N_GT][CAND_C];     // (val_bits<<32)|compact_id

__device__ int    d_gcand_idx[N_GT][GC_NEED];
__device__ int    d_gcand_cnt[N_GT];

__device__ unsigned d_colbm[NBMW];
__device__ int    d_rev[N_PRED];          // compact id -> orig col

// monotonic ascending key for float
__device__ __forceinline__ unsigned fkey(float f) {
    unsigned u = __float_as_uint(f);
    return (u & 0x80000000u) ? ~u : (u | 0x80000000u);
}

// block bitonic sort, ascending, n = power of two >= blockDim
__device__ __forceinline__ void bsort(ull* a, int n, int tid, int nth) {
    for (int k = 2; k <= n; k <<= 1) {
        for (int j = k >> 1; j > 0; j >>= 1) {
            for (int i = tid; i < n; i += nth) {
                int ixj = i ^ j;
                if (ixj > i) {
                    bool up = ((i & k) == 0);
                    ull x = a[i], y = a[ixj];
                    if ((x > y) == up) { a[i] = y; a[ixj] = x; }
                }
            }
            __syncthreads();
        }
    }
}

// ------------------- cost + giou matrices (validated fp32; labels decoded per block) ----
__global__ void k_cost(const float* __restrict__ pc, const float* __restrict__ ps,
                       const float* __restrict__ cls,
                       const float* __restrict__ gc, const float* __restrict__ gs,
                       const void* __restrict__ lab) {
    __shared__ float glo0[N_GT], glo1[N_GT], glo2[N_GT];
    __shared__ float ghi0[N_GT], ghi1[N_GT], ghi2[N_GT];
    __shared__ float gvol[N_GT];
    __shared__ int   glab[N_GT];
    __shared__ int   is32;
    int tid = threadIdx.x;  // blockDim = 512
    if (blockIdx.x == 0) {
        for (int i = tid; i < NBMW; i += blockDim.x) d_colbm[i] = 0u;
    }
    if (tid == 0) {
        const ull* p8 = (const ull*)lab;
        int f = 0;
        for (int i = 0; i < 64; i++) { if (p8[i] >> 32) { f = 1; break; } }
        is32 = f;
    }
    __syncthreads();
    if (tid < N_GT) {
        int t = tid;
        long long lv;
        if (is32) lv = (long long)((const int*)lab)[t];
        else      lv = ((const long long*)lab)[t];
        int iv = (int)lv;
        if (iv < 0) iv = 0;
        if (iv >= N_CLS) iv = N_CLS - 1;
        glab[t] = iv;
        float c0 = gc[t*3+0], c1 = gc[t*3+1], c2 = gc[t*3+2];
        float s0 = gs[t*3+0], s1 = gs[t*3+1], s2 = gs[t*3+2];
        float h0s = __fmul_rn(s0, 0.5f), h1s = __fmul_rn(s1, 0.5f), h2s = __fmul_rn(s2, 0.5f);
        float l0 = __fsub_rn(c0, h0s), l1 = __fsub_rn(c1, h1s), l2 = __fsub_rn(c2, h2s);
        float h0 = __fadd_rn(c0, h0s), h1 = __fadd_rn(c1, h1s), h2 = __fadd_rn(c2, h2s);
        glo0[t]=l0; glo1[t]=l1; glo2[t]=l2; ghi0[t]=h0; ghi1[t]=h1; ghi2[t]=h2;
        gvol[t] = __fmul_rn(__fmul_rn(__fsub_rn(h0,l0), __fsub_rn(h1,l1)), __fsub_rn(h2,l2));
    }
    __syncthreads();
    int p = blockIdx.x * 128 + (tid & 127);
    int gbase = (tid >> 7) * 32;          // 4 quarters of the g-loop
    float c0 = pc[p*3+0], c1 = pc[p*3+1], c2 = pc[p*3+2];
    float s0 = ps[p*3+0], s1 = ps[p*3+1], s2 = ps[p*3+2];
    float h0s = __fmul_rn(s0, 0.5f), h1s = __fmul_rn(s1, 0.5f), h2s = __fmul_rn(s2, 0.5f);
    float pl0 = __fsub_rn(c0, h0s), pl1 = __fsub_rn(c1, h1s), pl2 = __fsub_rn(c2, h2s);
    float ph0 = __fadd_rn(c0, h0s), ph1 = __fadd_rn(c1, h1s), ph2 = __fadd_rn(c2, h2s);
    float vol1 = __fmul_rn(__fmul_rn(__fsub_rn(ph0,pl0), __fsub_rn(ph1,pl1)), __fsub_rn(ph2,pl2));
    const float* clsrow = cls + (size_t)p * N_CLS;

    #pragma unroll 4
    for (int gi_ = 0; gi_ < 32; gi_++) {
        int g = gbase + gi_;
        float d0 = fmaxf(__fsub_rn(fminf(ph0, ghi0[g]), fmaxf(pl0, glo0[g])), 0.f);
        float d1 = fmaxf(__fsub_rn(fminf(ph1, ghi1[g]), fmaxf(pl1, glo1[g])), 0.f);
        float d2 = fmaxf(__fsub_rn(fminf(ph2, ghi2[g]), fmaxf(pl2, glo2[g])), 0.f);
        float ov = __fmul_rn(__fmul_rn(d0, d1), d2);
        float un = fmaxf(__fsub_rn(__fadd_rn(vol1, gvol[g]), ov), GEPS);
        float iou = __fdiv_rn(ov, un);
        float e0 = fmaxf(__fsub_rn(fmaxf(ph0, ghi0[g]), fminf(pl0, glo0[g])), 0.f);
        float e1 = fmaxf(__fsub_rn(fmaxf(ph1, ghi1[g]), fminf(pl1, glo1[g])), 0.f);
        float e2 = fmaxf(__fsub_rn(fmaxf(ph2, ghi2[g]), fminf(pl2, glo2[g])), 0.f);
        float enc = fmaxf(__fmul_rn(__fmul_rn(e0, e1), e2), GEPS);
        float gg = __fsub_rn(iou, __fdiv_rn(__fsub_rn(enc, un), enc));
        float cv = __ldg(clsrow + glab[g]);
        float sig = __fdiv_rn(1.0f, __fadd_rn(1.0f, expf(-cv)));
        d_giou[g][p] = gg;
        d_costm[g][p] = __fadd_rn(-sig, __fmul_rn(-2.0f, gg));
    }
}

// ------------------- selection: single-pass sample-threshold + sort -------------------
__global__ void k_select() {
    __shared__ ull buf[SEL_CAP];     // 32KB (aliased as hist in rare fallbacks)
    __shared__ ull samp[512];
    __shared__ float redf[512];
    __shared__ int s_cnt, s_c;

    int b = blockIdx.x, tid = threadIdx.x, nth = blockDim.x;  // nth = 512
    unsigned* hist = (unsigned*)buf;   // 2048-bin fallback histogram

    if (b < N_GT) {
        // ================= cost row =================
        int row = b;
        const float* crow = d_costm[row];
        if (tid < 512) {
            float v = crow[tid * 128];
            samp[tid] = ((ull)fkey(v) << 32) | (unsigned)(tid * 128);
        }
        __syncthreads();
        bsort(samp, 512, tid, nth);

        const int slist[5] = {4, 16, 64, 255, 511};
        int si = 0, cc = 0, truecnt = 0;
        while (true) {
            if (tid == 0) s_cnt = 0;
            __syncthreads();
            unsigned Tkey = (unsigned)(samp[slist[si]] >> 32);
            for (int j = tid; j < N_PRED; j += nth) {
                unsigned k = fkey(crow[j]);
                if (k <= Tkey) {
                    int slot = atomicAdd(&s_cnt, 1);
                    if (slot < SEL_CAP) buf[slot] = ((ull)k << 32) | (unsigned)j;
                }
            }
            __syncthreads();
            truecnt = s_cnt;
            cc = (truecnt < SEL_CAP) ? truecnt : SEL_CAP;
            if (truecnt >= CAND_C && truecnt <= SEL_CAP) break;
            if (truecnt > SEL_CAP) {
                for (int i = tid; i < 2048; i += nth) hist[i] = 0;
                __syncthreads();
                for (int j = tid; j < N_PRED; j += nth)
                    atomicAdd(&hist[fkey(crow[j]) >> 21], 1u);
                __syncthreads();
                if (tid == 0) {
                    unsigned need = CAND_C, cum = 0; int bb = 0;
                    for (; bb < 2047; bb++) { if (cum + hist[bb] >= need) break; cum += hist[bb]; }
                    s_c = bb; s_cnt = (int)(need - cum);
                }
                __syncthreads();
                unsigned pfx11 = (unsigned)s_c; int need1 = s_cnt;
                __syncthreads();
                for (int i = tid; i < 2048; i += nth) hist[i] = 0;
                __syncthreads();
                for (int j = tid; j < N_PRED; j += nth) {
                    unsigned k = fkey(crow[j]);
                    if ((k >> 21) == pfx11) atomicAdd(&hist[(k >> 10) & 2047u], 1u);
                }
                __syncthreads();
                if (tid == 0) {
                    unsigned need = (unsigned)need1, cum = 0; int bb = 0;
                    for (; bb < 2047; bb++) { if (cum + hist[bb] >= need) break; cum += hist[bb]; }
                    s_c = (int)((pfx11 << 11) | (unsigned)bb);
                    s_cnt = 0;
                }
                __syncthreads();
                unsigned pfx22 = (unsigned)s_c;
                __syncthreads();
                for (int j = tid; j < N_PRED; j += nth) {
                    unsigned k = fkey(crow[j]);
                    if ((k >> 10) <= pfx22) {
                        int slot = atomicAdd(&s_cnt, 1);
                        if (slot < SEL_CAP) buf[slot] = ((ull)k << 32) | (unsigned)j;
                    }
                }
                __syncthreads();
                truecnt = s_cnt;
                cc = (truecnt < SEL_CAP) ? truecnt : SEL_CAP;
                break;
            }
            si++;
            if (si >= 5) break;
            __syncthreads();
        }
        int n2 = 512; while (n2 < cc) n2 <<= 1;
        for (int i = tid + cc; i < n2; i += nth) buf[i] = 0xFFFFFFFFFFFFFFFFull;
        __syncthreads();
        bsort(buf, n2, tid, nth);
        int keep = (cc < CAND_C) ? cc : CAND_C;
        for (int i = tid; i < keep; i += nth) {
            ull e = buf[i];
            int j = (int)(e & 0xFFFFFFFFull);
            d_ccand_idx[row][i] = j;
            d_ccand_val[row][i] = crow[j];
            atomicOr(&d_colbm[j >> 5], 1u << (j & 31));
        }
        if (tid == 0) d_ccand_cnt[row] = keep;
    } else {
        // ================= giou row: fused max + collect =================
        int row = b - N_GT;
        const float* grow = d_giou[row];
        if (tid == 0) s_cnt = 0;
        __syncthreads();
        float lmax = -1e30f;
        for (int j = tid; j < N_PRED; j += nth) {
            float g = grow[j];
            lmax = fmaxf(lmax, g);
            if (g > IOU_THRES) {
                int slot = atomicAdd(&s_cnt, 1);
                if (slot < SEL_CAP) buf[slot] = ((ull)(~fkey(g)) << 32) | (unsigned)j;
            }
        }
        redf[tid] = lmax;
        __syncthreads();
        for (int off = nth >> 1; off > 0; off >>= 1) {
            if (tid < off) redf[tid] = fmaxf(redf[tid], redf[tid + off]);
            __syncthreads();
        }
        if (tid == 0) d_maxg[row] = redf[0];
        int tot = s_cnt;
        __syncthreads();
        if (tot > SEL_CAP) {
            for (int i = tid; i < 2048; i += nth) hist[i] = 0;
            __syncthreads();
            for (int j = tid; j < N_PRED; j += nth) {
                float g = grow[j];
                if (g > IOU_THRES) atomicAdd(&hist[(~fkey(g)) >> 21], 1u);
            }
            __syncthreads();
            if (tid == 0) {
                unsigned need = GC_NEED, cum = 0; int bb = 0;
                for (; bb < 2047; bb++) { if (cum + hist[bb] >= need) break; cum += hist[bb]; }
                s_c = bb; s_cnt = (int)(need - cum);
            }
            __syncthreads();
            unsigned pfx11 = (unsigned)s_c; int need1 = s_cnt;
            __syncthreads();
            for (int i = tid; i < 2048; i += nth) hist[i] = 0;
            __syncthreads();
            for (int j = tid; j < N_PRED; j += nth) {
                float g = grow[j];
                if (g > IOU_THRES) {
                    unsigned k = ~fkey(g);
                    if ((k >> 21) == pfx11) atomicAdd(&hist[(k >> 10) & 2047u], 1u);
                }
            }
            __syncthreads();
            if (tid == 0) {
                unsigned need = (unsigned)need1, cum = 0; int bb = 0;
                for (; bb < 2047; bb++) { if (cum + hist[bb] >= need) break; cum += hist[bb]; }
                s_c = (int)((pfx11 << 11) | (unsigned)bb);
                s_cnt = 0;
            }
            __syncthreads();
            unsigned pfx22 = (unsigned)s_c;
            __syncthreads();
            for (int j = tid; j < N_PRED; j += nth) {
                float g = grow[j];
                if (!(g > IOU_THRES)) continue;
                unsigned k = ~fkey(g);
                if ((k >> 10) <= pfx22) {
                    int slot = atomicAdd(&s_cnt, 1);
                    if (slot < SEL_CAP) buf[slot] = ((ull)k << 32) | (unsigned)j;
                }
            }
            __syncthreads();
            tot = s_cnt;
        }
        int cc = (tot < SEL_CAP) ? tot : SEL_CAP;
        int n2 = 512; while (n2 < cc) n2 <<= 1;
        for (int i = tid + cc; i < n2; i += nth) buf[i] = 0xFFFFFFFFFFFFFFFFull;
        __syncthreads();
        bsort(buf, n2, tid, nth);   // key asc == giou desc, idx asc
        int cnt = (cc < GC_NEED) ? cc : GC_NEED;
        for (int i = tid; i < cnt; i += nth)
            d_gcand_idx[row][i] = (int)(buf[i] & 0xFFFFFFFFull);
        if (tid == 0) d_gcand_cnt[row] = cnt;
    }
}

// ------------------- LSA (slot-based smem state) + dynamic assign + output -----------
__global__ void k_lsa(float* __restrict__ out) {
    extern __shared__ unsigned char dsm[];
    uint16_t* shSlot = (uint16_t*)(dsm + OFF_SLOT);   // cid -> slot (0xFFFF = untouched)
    double*   sDist  = (double*)(dsm + OFF_DIST);
    uint8_t*  sPath  = (uint8_t*)(dsm + OFF_PATH);
    uint16_t* sCol   = (uint16_t*)(dsm + OFF_COL);    // slot -> cid
    unsigned* sSC    = (unsigned*)(dsm + OFF_SC);     // per-slot SC bits
    uint8_t*  shR    = (uint8_t*)(dsm + OFF_R);       // cid -> row (255 = free)
    uint16_t* vslot  = (uint16_t*)(dsm + OFF_VSLOT);  // cid -> v slot (0xFFFF = v==0)
    double*   vval   = (double*)(dsm + OFF_VVAL);
    int*      cbase  = (int*)(dsm + OFF_SLOT);        // alias during prologue only

    __shared__ double u[N_GT];
    __shared__ int SR[N_GT];
    __shared__ int c4r[N_GT];
    __shared__ int pend[N_GT];
    __shared__ int scnt[N_GT];
    __shared__ float s0val[N_GT];
    __shared__ int   s0idx[N_GT];
    __shared__ int   colro[N_GT];
    __shared__ double rv[8];
    __shared__ int rc[8];
    __shared__ int tsum[256];
    __shared__ int s_row, s_sink, s_tcnt, s_vcnt, s_npend, s_nSR;
    __shared__ double s_minval;

    int tid = threadIdx.x, nth = blockDim.x;  // 256
    const double DINF = 1e300;

    // ---- compact scan of column bitmap (cbase aliases shSlot region) ----
    int wbase = tid * 8;
    int cnts8[8]; int ssum = 0;
    #pragma unroll
    for (int w = 0; w < 8; w++) { cnts8[w] = __popc(d_colbm[wbase + w]); ssum += cnts8[w]; }
    tsum[tid] = ssum;
    __syncthreads();
    for (int off = 1; off < 256; off <<= 1) {
        int v_ = 0;
        if (tid >= off) v_ = tsum[tid - off];
        __syncthreads();
        tsum[tid] += v_;
        __syncthreads();
    }
    int excl = tsum[tid] - ssum;
    #pragma unroll
    for (int w = 0; w < 8; w++) { cbase[wbase + w] = excl; excl += cnts8[w]; }
    __syncthreads();
    int nK = tsum[255];
    if (nK > LSA_CAP) nK = LSA_CAP;   // impossible (union <= 16384), safety only

    // ---- remap: build packed (val|cid) candidates + reverse map ----
    for (int x = tid; x < N_GT * CAND_C; x += nth) {
        int row = x >> 7, s = x & 127;
        if (s < d_ccand_cnt[row]) {
            int j = d_ccand_idx[row][s];
            int w = j >> 5;
            int cid = cbase[w] + __popc(d_colbm[w] & ((1u << (j & 31)) - 1u));
            float v_ = d_ccand_val[row][s];
            d_ccpack[row][s] = ((ull)__float_as_uint(v_) << 32) | (unsigned)cid;
            d_rev[cid] = j;
        }
    }
    __syncthreads();   // cbase dead; shSlot region free

    // ---- init smem state ----
    {
        unsigned* p32 = (unsigned*)shSlot;
        for (int i = tid; i < LSA_CAP/2; i += nth) p32[i] = 0xFFFFFFFFu;
        unsigned* q32 = (unsigned*)vslot;
        for (int i = tid; i < LSA_CAP/2; i += nth) q32[i] = 0xFFFFFFFFu;
    }
    for (int i = tid; i < nK; i += nth) shR[i] = 0xFF;
    for (int i = tid; i < SLOT_CAP/32; i += nth) sSC[i] = 0;
    if (tid < N_GT) {
        c4r[tid] = -1;
        scnt[tid] = d_ccand_cnt[tid];
        ull pk = d_ccpack[tid][0];
        s0idx[tid] = (int)(pk & 0xFFFFFFFFull);
        s0val[tid] = __uint_as_float((unsigned)(pk >> 32));
    }
    if (tid == 0) s_vcnt = 0;
    __syncthreads();

    // ---- greedy tight assignment (pure smem, serial) ----
    if (tid == 0) {
        s_npend = 0;
        for (int i = 0; i < N_GT; i++) {
            if (scnt[i] > 0) {
                u[i] = (double)s0val[i];
                int j = s0idx[i];
                if (j >= 0 && j < nK && shR[j] == 0xFF) {
                    shR[j] = (uint8_t)i; c4r[i] = j;
                    continue;
                }
            } else u[i] = 0.0;
            pend[s_npend++] = i;
        }
    }
    __syncthreads();
    int npend = s_npend;

    // ---- block-wide shortest augmenting path per conflicted row ----
    for (int pi = 0; pi < npend; pi++) {
        int cur = pend[pi];
        if (tid == 0) { s_row = cur; s_sink = -1; s_tcnt = 0; s_nSR = 0; s_minval = 0.0; }
        __syncthreads();
        for (int step = 0; step < N_GT; step++) {
            int i = s_row;
            if (tid == 0) SR[s_nSR++] = i;
            double mv0 = s_minval, ui = u[i];
            int cnt = scnt[i];
            for (int s = tid; s < cnt; s += nth) {
                ull pk = d_ccpack[i][s];
                int cid = (int)(pk & 0xFFFFFFFFull);
                int slot = shSlot[cid];
                if (slot != 0xFFFF && ((sSC[slot >> 5] >> (slot & 31)) & 1u)) continue;
                int vs = vslot[cid];
                double v_ = (vs != 0xFFFF) ? vval[vs] : 0.0;
                double r = ((mv0 + (double)__uint_as_float((unsigned)(pk >> 32))) - ui) - v_;
                if (slot == 0xFFFF) {
                    int t2 = atomicAdd(&s_tcnt, 1);
                    if (t2 < SLOT_CAP) {
                        shSlot[cid] = (uint16_t)t2;
                        sCol[t2] = (uint16_t)cid;
                        sDist[t2] = r;
                        sPath[t2] = (uint8_t)i;
                    }
                } else if (r < sDist[slot]) {
                    sDist[slot] = r; sPath[slot] = (uint8_t)i;
                }
            }
            __syncthreads();
            int tcnt = s_tcnt; if (tcnt > SLOT_CAP) tcnt = SLOT_CAP;
            double bv = DINF; int bc = 0x7fffffff;
            for (int t2 = tid; t2 < tcnt; t2 += nth) {
                if ((sSC[t2 >> 5] >> (t2 & 31)) & 1u) continue;
                double sv = sDist[t2];
                int cid = sCol[t2];
                if (sv < bv || (sv == bv && cid < bc)) { bv = sv; bc = cid; }
            }
            #pragma unroll
            for (int off = 16; off > 0; off >>= 1) {
                double ov = __shfl_down_sync(0xffffffffu, bv, off);
                int   oc = __shfl_down_sync(0xffffffffu, bc, off);
                if (ov < bv || (ov == bv && oc < bc)) { bv = ov; bc = oc; }
            }
            if ((tid & 31) == 0) { rv[tid >> 5] = bv; rc[tid >> 5] = bc; }
            __syncthreads();
            if (tid == 0) {
                double fbv = rv[0]; int fbc = rc[0];
                #pragma unroll
                for (int k = 1; k < 8; k++) {
                    if (rv[k] < fbv || (rv[k] == fbv && rc[k] < fbc)) { fbv = rv[k]; fbc = rc[k]; }
                }
                if (fbc >= 0 && fbc < nK) {
                    s_minval = fbv;
                    int slot = shSlot[fbc];
                    sSC[slot >> 5] |= (1u << (slot & 31));
                    int r4 = shR[fbc];
                    if (r4 == 0xFF) s_sink = fbc; else s_row = r4;
                } else s_sink = -2;
            }
            __syncthreads();
            if (s_sink != -1) break;
        }
        if (s_sink >= 0) {
            double mv = s_minval;
            if (tid == 0) {
                u[cur] += mv;
                for (int k = 1; k < s_nSR; k++) {
                    int i2 = SR[k];
                    u[i2] += mv - sDist[shSlot[c4r[i2]]];
                }
            }
            int tcnt = s_tcnt; if (tcnt > SLOT_CAP) tcnt = SLOT_CAP;
            for (int t2 = tid; t2 < tcnt; t2 += nth) {
                if ((sSC[t2 >> 5] >> (t2 & 31)) & 1u) {
                    int cid = sCol[t2];
                    int vs = vslot[cid];
                    if (vs == 0xFFFF) {
                        vs = atomicAdd(&s_vcnt, 1);
                        if (vs < VV_CAP) { vslot[cid] = (uint16_t)vs; vval[vs] = 0.0; }
                    }
                    if (vs < VV_CAP) vval[vs] -= mv - sDist[t2];
                }
            }
            __syncthreads();
            if (tid == 0) {
                int j = s_sink;
                for (int it = 0; it <= N_GT && j >= 0; it++) {
                    int i2 = sPath[shSlot[j]];
                    shR[j] = (uint8_t)i2;
                    int tmp = c4r[i2];
                    c4r[i2] = j;
                    j = tmp;
                    if (i2 == cur) break;
                }
            }
        }
        __syncthreads();
        // reset touched state for next augmentation
        {
            unsigned* p32 = (unsigned*)shSlot;
            for (int i = tid; i < LSA_CAP/2; i += nth) p32[i] = 0xFFFFFFFFu;
            int tw = (s_tcnt < SLOT_CAP ? s_tcnt : SLOT_CAP);
            for (int i = tid; i < (tw + 31) / 32; i += nth) sSC[i] = 0;
        }
        __syncthreads();
    }
    if (tid < N_GT) colro[tid] = (c4r[tid] >= 0) ? d_rev[c4r[tid]] : -1;
    __syncthreads();

    // ================= dynamic assignment phase (reuses dead dsm region) =================
    unsigned* used = (unsigned*)dsm;                    // 8KB @ 0
    int* res_p = (int*)(dsm + 8192);                    // 5632B
    int* res_g = (int*)(dsm + 13824);                   // 5632B
    int* pref  = (int*)(dsm + 19456);                   // 16KB: pref[g*32+s], depth 32
    int* gcnts = (int*)(dsm + 35840);                   // 512B
    int* ordv  = (int*)(dsm + 36352);                   // 512B
    float* mg  = (float*)(dsm + 36864);                 // 512B

    for (int i = tid; i < NBMW; i += nth) used[i] = 0;
    if (tid < N_GT) { gcnts[tid] = d_gcand_cnt[tid]; mg[tid] = d_maxg[tid]; }
    __syncthreads();
    if (tid < N_GT) {
        float mv = mg[tid]; int r = 0;
        for (int j = 0; j < N_GT; j++) {
            float o = mg[j];
            if (o < mv || (o == mv && j < tid)) r++;
        }
        ordv[r] = tid;
    }
    for (int i = tid; i < N_GT * 32; i += nth) {
        int g = i >> 5, s = i & 31;
        pref[i] = (s < gcnts[g]) ? d_gcand_idx[g][s] : -1;
    }
    if (tid < N_GT) {
        int p = colro[tid];
        if (p >= 0 && p < N_PRED) atomicOr(&used[p >> 5], 1u << (p & 31));
        res_p[tid] = p;
        res_g[tid] = tid;
    }
    __syncthreads();
    if (tid < 32) {
        int lane = tid;
        for (int t = 0; t < N_GT; t++) {
            int g = ordv[t];
            int cnt = gcnts[g];
            int picked = 0;
            for (int base = 0; base < cnt && picked < MAX_DYN; base += 32) {
                int idx = -1;
                if (base + lane < cnt)
                    idx = (base == 0) ? pref[g * 32 + lane] : d_gcand_idx[g][base + lane];
                bool elig = (idx >= 0) && (idx < N_PRED) && !((used[idx >> 5] >> (idx & 31)) & 1u);
                unsigned m = __ballot_sync(0xffffffffu, elig);
                int K = MAX_DYN - picked;
                int pre = __popc(m & ((1u << lane) - 1u));
                if (elig && pre < K) {
                    atomicOr(&used[idx >> 5], 1u << (idx & 31));
                    res_p[128 + t * MAX_DYN + picked + pre] = idx;
                    res_g[128 + t * MAX_DYN + picked + pre] = g;
                }
                int got = __popc(m); if (got > K) got = K;
                picked += got;
                __syncwarp();
            }
            if (lane >= picked && lane < MAX_DYN) {
                res_p[128 + t * MAX_DYN + lane] = -1;
                res_g[128 + t * MAX_DYN + lane] = -1;
            }
            __syncwarp();
        }
    }
    __syncthreads();
    for (int i = tid; i < 1408; i += nth) {
        out[i]        = (float)res_p[i];
        out[1408 + i] = (float)res_g[i];
    }
}

// ------------------- launch (inputs resolved by element count) -------------------
extern "C" void kernel_launch(void* const* d_in, const int* in_sizes, int n_in,
                              void* d_out, int out_size) {
    const float* all_centers = 0;
    const float* all_sizes   = 0;
    const float* all_cls     = 0;
    const float* gt_centers  = 0;
    const float* gt_sizes    = 0;
    const void*  gt_labels   = 0;
    int seen196 = 0, seen384 = 0;
    for (int i = 0; i < n_in; i++) {
        long long s = in_sizes[i];
        if (s == (long long)N_PRED * N_CLS) {
            all_cls = (const float*)d_in[i];
        } else if (s == (long long)N_PRED * 3) {
            if (seen196++ == 0) all_centers = (const float*)d_in[i];
            else                all_sizes   = (const float*)d_in[i];
        } else if (s == (long long)N_GT * 3) {
            if (seen384++ == 0) gt_centers = (const float*)d_in[i];
            else                gt_sizes   = (const float*)d_in[i];
        } else if (s == (long long)N_GT) {
            gt_labels = d_in[i];
        }
    }

    cudaFuncSetAttribute(k_lsa, cudaFuncAttributeMaxDynamicSharedMemorySize, LSA_DYN_BYTES);

    k_cost<<<N_PRED / 128, 512>>>(all_centers, all_sizes, all_cls, gt_centers, gt_sizes, gt_labels);
    k_select<<<2 * N_GT, 512>>>();
    k_lsa<<<1, 256, LSA_DYN_BYTES>>>((float*)d_out);
}

// round 12
// speedup vs baseline: 1.2346x; 1.0719x over previous
#include <cuda_runtime.h>
#include <math.h>
#include <stdint.h>

#define N_PRED 65536
#define N_GT   128
#define N_CLS  256
#define MAX_DYN 10
#define GEPS   1e-6f
#define IOU_THRES 0.25f
#define CAND_C 128      // per-row LSA candidates: exactly the 128 smallest
#define SEL_CAP 4096    // collection buffer cap (smem)
#define GC_NEED 1408    // per-gt dynamic candidate depth (10 + 128 + 10*127)
#define NBMW   (N_PRED/32)   // 2048 bitmap words
#define LSA_CAP 16512        // compact column universe cap; union <= 16384
#define SLOT_CAP 8192        // touched-column slots per augmentation
#define VV_CAP   2048        // nonzero-dual slots (persistent)

// dynamic smem layout for k_lsa
#define OFF_SLOT   0                         // u16[LSA_CAP]          33024
#define OFF_DIST   33024                     // f64[SLOT_CAP]         65536
#define OFF_PATH   98560                     // u8[SLOT_CAP]           8192
#define OFF_COL    106752                    // u16[SLOT_CAP]         16384
#define OFF_SC     123136                    // u32[SLOT_CAP/32]       1024
#define OFF_R      124160                    // u8[LSA_CAP]           16512
#define OFF_VSLOT  140672                    // u16[LSA_CAP]          33024
#define OFF_VVAL   173696                    // f64[VV_CAP]           16384
#define LSA_DYN_BYTES 190080

typedef unsigned long long ull;

// ------------------- scratch (device globals; no runtime allocation) -------------------
__device__ float  d_giou[N_GT][N_PRED];   // 32MB  giou_T[g][p]
__device__ float  d_costm[N_GT][N_PRED];  // 32MB  cost_T[g][p]
__device__ float  d_maxg[N_GT];

__device__ int    d_ccand_idx[N_GT][CAND_C];  // orig col ids, sorted (cost,idx) asc
__device__ float  d_ccand_val[N_GT][CAND_C];
__device__ int    d_ccand_cnt[N_GT];
__device__ ull    d_ccpack[N_GT][CAND_C];     // (val_bits<<32)|compact_id

__device__ int    d_gcand_idx[N_GT][GC_NEED];
__device__ int    d_gcand_cnt[N_GT];

__device__ unsigned d_colbm[NBMW];
__device__ int    d_rev[N_PRED];          // compact id -> orig col

// monotonic ascending key for float
__device__ __forceinline__ unsigned fkey(float f) {
    unsigned u = __float_as_uint(f);
    return (u & 0x80000000u) ? ~u : (u | 0x80000000u);
}

// block bitonic sort, ascending, n = power of two >= blockDim
__device__ __forceinline__ void bsort(ull* a, int n, int tid, int nth) {
    for (int k = 2; k <= n; k <<= 1) {
        for (int j = k >> 1; j > 0; j >>= 1) {
            for (int i = tid; i < n; i += nth) {
                int ixj = i ^ j;
                if (ixj > i) {
                    bool up = ((i & k) == 0);
                    ull x = a[i], y = a[ixj];
                    if ((x > y) == up) { a[i] = y; a[ixj] = x; }
                }
            }
            __syncthreads();
        }
    }
}

// ------------------- cost + giou matrices (validated fp32; float4-packed gt tables) ----
__global__ void k_cost(const float* __restrict__ pc, const float* __restrict__ ps,
                       const float* __restrict__ cls,
                       const float* __restrict__ gc, const float* __restrict__ gs,
                       const void* __restrict__ lab) {
    __shared__ float4 gp1[N_GT];  // lo0, lo1, lo2, gvol
    __shared__ float4 gp2[N_GT];  // hi0, hi1, hi2, label_bits
    __shared__ int   is32;
    int tid = threadIdx.x;  // blockDim = 512
    if (blockIdx.x == 0) {
        for (int i = tid; i < NBMW; i += blockDim.x) d_colbm[i] = 0u;
    }
    if (tid == 0) {
        const ull* p8 = (const ull*)lab;
        int f = 0;
        for (int i = 0; i < 64; i++) { if (p8[i] >> 32) { f = 1; break; } }
        is32 = f;
    }
    __syncthreads();
    if (tid < N_GT) {
        int t = tid;
        long long lv;
        if (is32) lv = (long long)((const int*)lab)[t];
        else      lv = ((const long long*)lab)[t];
        int iv = (int)lv;
        if (iv < 0) iv = 0;
        if (iv >= N_CLS) iv = N_CLS - 1;
        float c0 = gc[t*3+0], c1 = gc[t*3+1], c2 = gc[t*3+2];
        float s0 = gs[t*3+0], s1 = gs[t*3+1], s2 = gs[t*3+2];
        float h0s = __fmul_rn(s0, 0.5f), h1s = __fmul_rn(s1, 0.5f), h2s = __fmul_rn(s2, 0.5f);
        float l0 = __fsub_rn(c0, h0s), l1 = __fsub_rn(c1, h1s), l2 = __fsub_rn(c2, h2s);
        float h0 = __fadd_rn(c0, h0s), h1 = __fadd_rn(c1, h1s), h2 = __fadd_rn(c2, h2s);
        float gv = __fmul_rn(__fmul_rn(__fsub_rn(h0,l0), __fsub_rn(h1,l1)), __fsub_rn(h2,l2));
        gp1[t] = make_float4(l0, l1, l2, gv);
        gp2[t] = make_float4(h0, h1, h2, __int_as_float(iv));
    }
    __syncthreads();
    int p = blockIdx.x * 128 + (tid & 127);
    int gbase = (tid >> 7) * 32;          // 4 quarters of the g-loop
    float c0 = pc[p*3+0], c1 = pc[p*3+1], c2 = pc[p*3+2];
    float s0 = ps[p*3+0], s1 = ps[p*3+1], s2 = ps[p*3+2];
    float h0s = __fmul_rn(s0, 0.5f), h1s = __fmul_rn(s1, 0.5f), h2s = __fmul_rn(s2, 0.5f);
    float pl0 = __fsub_rn(c0, h0s), pl1 = __fsub_rn(c1, h1s), pl2 = __fsub_rn(c2, h2s);
    float ph0 = __fadd_rn(c0, h0s), ph1 = __fadd_rn(c1, h1s), ph2 = __fadd_rn(c2, h2s);
    float vol1 = __fmul_rn(__fmul_rn(__fsub_rn(ph0,pl0), __fsub_rn(ph1,pl1)), __fsub_rn(ph2,pl2));
    const float* clsrow = cls + (size_t)p * N_CLS;

    #pragma unroll 4
    for (int gi_ = 0; gi_ < 32; gi_++) {
        int g = gbase + gi_;
        float4 A = gp1[g];
        float4 B = gp2[g];
        float d0 = fmaxf(__fsub_rn(fminf(ph0, B.x), fmaxf(pl0, A.x)), 0.f);
        float d1 = fmaxf(__fsub_rn(fminf(ph1, B.y), fmaxf(pl1, A.y)), 0.f);
        float d2 = fmaxf(__fsub_rn(fminf(ph2, B.z), fmaxf(pl2, A.z)), 0.f);
        float ov = __fmul_rn(__fmul_rn(d0, d1), d2);
        float un = fmaxf(__fsub_rn(__fadd_rn(vol1, A.w), ov), GEPS);
        float iou = __fdiv_rn(ov, un);
        float e0 = fmaxf(__fsub_rn(fmaxf(ph0, B.x), fminf(pl0, A.x)), 0.f);
        float e1 = fmaxf(__fsub_rn(fmaxf(ph1, B.y), fminf(pl1, A.y)), 0.f);
        float e2 = fmaxf(__fsub_rn(fmaxf(ph2, B.z), fminf(pl2, A.z)), 0.f);
        float enc = fmaxf(__fmul_rn(__fmul_rn(e0, e1), e2), GEPS);
        float gg = __fsub_rn(iou, __fdiv_rn(__fsub_rn(enc, un), enc));
        float cv = __ldg(clsrow + __float_as_int(B.w));
        float sig = __fdiv_rn(1.0f, __fadd_rn(1.0f, expf(-cv)));
        d_giou[g][p] = gg;
        d_costm[g][p] = __fadd_rn(-sig, __fmul_rn(-2.0f, gg));
    }
}

// ------------------- selection: single-pass sample-threshold + sort (vectorized) -------
__global__ void k_select() {
    __shared__ ull buf[SEL_CAP];     // 32KB (aliased as hist in rare fallbacks)
    __shared__ ull samp[512];
    __shared__ float redf[512];
    __shared__ int s_cnt, s_c;

    int b = blockIdx.x, tid = threadIdx.x, nth = blockDim.x;  // nth = 512
    unsigned* hist = (unsigned*)buf;   // 2048-bin fallback histogram

    if (b < N_GT) {
        // ================= cost row =================
        int row = b;
        const float* crow = d_costm[row];
        const float4* crow4 = (const float4*)crow;
        if (tid < 512) {
            float v = crow[tid * 128];
            samp[tid] = ((ull)fkey(v) << 32) | (unsigned)(tid * 128);
        }
        __syncthreads();
        bsort(samp, 512, tid, nth);

        const int slist[5] = {4, 16, 64, 255, 511};
        int si = 0, cc = 0, truecnt = 0;
        while (true) {
            if (tid == 0) s_cnt = 0;
            __syncthreads();
            unsigned Tkey = (unsigned)(samp[slist[si]] >> 32);
            for (int j4 = tid; j4 < N_PRED / 4; j4 += nth) {
                float4 v4 = crow4[j4];
                int j = j4 * 4;
                unsigned k0 = fkey(v4.x), k1 = fkey(v4.y), k2 = fkey(v4.z), k3 = fkey(v4.w);
                if (k0 <= Tkey) { int s = atomicAdd(&s_cnt, 1); if (s < SEL_CAP) buf[s] = ((ull)k0 << 32) | (unsigned)(j+0); }
                if (k1 <= Tkey) { int s = atomicAdd(&s_cnt, 1); if (s < SEL_CAP) buf[s] = ((ull)k1 << 32) | (unsigned)(j+1); }
                if (k2 <= Tkey) { int s = atomicAdd(&s_cnt, 1); if (s < SEL_CAP) buf[s] = ((ull)k2 << 32) | (unsigned)(j+2); }
                if (k3 <= Tkey) { int s = atomicAdd(&s_cnt, 1); if (s < SEL_CAP) buf[s] = ((ull)k3 << 32) | (unsigned)(j+3); }
            }
            __syncthreads();
            truecnt = s_cnt;
            cc = (truecnt < SEL_CAP) ? truecnt : SEL_CAP;
            if (truecnt >= CAND_C && truecnt <= SEL_CAP) break;
            if (truecnt > SEL_CAP) {
                // rare: tie-heavy. exact 2-level 2048-bin histogram for the 128th key.
                for (int i = tid; i < 2048; i += nth) hist[i] = 0;
                __syncthreads();
                for (int j = tid; j < N_PRED; j += nth)
                    atomicAdd(&hist[fkey(crow[j]) >> 21], 1u);
                __syncthreads();
                if (tid == 0) {
                    unsigned need = CAND_C, cum = 0; int bb = 0;
                    for (; bb < 2047; bb++) { if (cum + hist[bb] >= need) break; cum += hist[bb]; }
                    s_c = bb; s_cnt = (int)(need - cum);
                }
                __syncthreads();
                unsigned pfx11 = (unsigned)s_c; int need1 = s_cnt;
                __syncthreads();
                for (int i = tid; i < 2048; i += nth) hist[i] = 0;
                __syncthreads();
                for (int j = tid; j < N_PRED; j += nth) {
                    unsigned k = fkey(crow[j]);
                    if ((k >> 21) == pfx11) atomicAdd(&hist[(k >> 10) & 2047u], 1u);
                }
                __syncthreads();
                if (tid == 0) {
                    unsigned need = (unsigned)need1, cum = 0; int bb = 0;
                    for (; bb < 2047; bb++) { if (cum + hist[bb] >= need) break; cum += hist[bb]; }
                    s_c = (int)((pfx11 << 11) | (unsigned)bb);
                    s_cnt = 0;
                }
                __syncthreads();
                unsigned pfx22 = (unsigned)s_c;
                __syncthreads();
                for (int j = tid; j < N_PRED; j += nth) {
                    unsigned k = fkey(crow[j]);
                    if ((k >> 10) <= pfx22) {
                        int slot = atomicAdd(&s_cnt, 1);
                        if (slot < SEL_CAP) buf[slot] = ((ull)k << 32) | (unsigned)j;
                    }
                }
                __syncthreads();
                truecnt = s_cnt;
                cc = (truecnt < SEL_CAP) ? truecnt : SEL_CAP;
                break;
            }
            si++;
            if (si >= 5) break;
            __syncthreads();
        }
        int n2 = 512; while (n2 < cc) n2 <<= 1;
        for (int i = tid + cc; i < n2; i += nth) buf[i] = 0xFFFFFFFFFFFFFFFFull;
        __syncthreads();
        bsort(buf, n2, tid, nth);
        int keep = (cc < CAND_C) ? cc : CAND_C;
        for (int i = tid; i < keep; i += nth) {
            ull e = buf[i];
            int j = (int)(e & 0xFFFFFFFFull);
            d_ccand_idx[row][i] = j;
            d_ccand_val[row][i] = crow[j];
            atomicOr(&d_colbm[j >> 5], 1u << (j & 31));
        }
        if (tid == 0) d_ccand_cnt[row] = keep;
    } else {
        // ================= giou row: fused max + collect (vectorized) =================
        int row = b - N_GT;
        const float* grow = d_giou[row];
        const float4* grow4 = (const float4*)grow;
        if (tid == 0) s_cnt = 0;
        __syncthreads();
        float lmax = -1e30f;
        for (int j4 = tid; j4 < N_PRED / 4; j4 += nth) {
            float4 g4 = grow4[j4];
            int j = j4 * 4;
            lmax = fmaxf(lmax, fmaxf(fmaxf(g4.x, g4.y), fmaxf(g4.z, g4.w)));
            if (g4.x > IOU_THRES) { int s = atomicAdd(&s_cnt, 1); if (s < SEL_CAP) buf[s] = ((ull)(~fkey(g4.x)) << 32) | (unsigned)(j+0); }
            if (g4.y > IOU_THRES) { int s = atomicAdd(&s_cnt, 1); if (s < SEL_CAP) buf[s] = ((ull)(~fkey(g4.y)) << 32) | (unsigned)(j+1); }
            if (g4.z > IOU_THRES) { int s = atomicAdd(&s_cnt, 1); if (s < SEL_CAP) buf[s] = ((ull)(~fkey(g4.z)) << 32) | (unsigned)(j+2); }
            if (g4.w > IOU_THRES) { int s = atomicAdd(&s_cnt, 1); if (s < SEL_CAP) buf[s] = ((ull)(~fkey(g4.w)) << 32) | (unsigned)(j+3); }
        }
        redf[tid] = lmax;
        __syncthreads();
        for (int off = nth >> 1; off > 0; off >>= 1) {
            if (tid < off) redf[tid] = fmaxf(redf[tid], redf[tid + off]);
            __syncthreads();
        }
        if (tid == 0) d_maxg[row] = redf[0];
        int tot = s_cnt;
        __syncthreads();
        if (tot > SEL_CAP) {
            // rare overflow: 2-level histogram over qualifiers, then bounded re-collect
            for (int i = tid; i < 2048; i += nth) hist[i] = 0;
            __syncthreads();
            for (int j = tid; j < N_PRED; j += nth) {
                float g = grow[j];
                if (g > IOU_THRES) atomicAdd(&hist[(~fkey(g)) >> 21], 1u);
            }
            __syncthreads();
            if (tid == 0) {
                unsigned need = GC_NEED, cum = 0; int bb = 0;
                for (; bb < 2047; bb++) { if (cum + hist[bb] >= need) break; cum += hist[bb]; }
                s_c = bb; s_cnt = (int)(need - cum);
            }
            __syncthreads();
            unsigned pfx11 = (unsigned)s_c; int need1 = s_cnt;
            __syncthreads();
            for (int i = tid; i < 2048; i += nth) hist[i] = 0;
            __syncthreads();
            for (int j = tid; j < N_PRED; j += nth) {
                float g = grow[j];
                if (g > IOU_THRES) {
                    unsigned k = ~fkey(g);
                    if ((k >> 21) == pfx11) atomicAdd(&hist[(k >> 10) & 2047u], 1u);
                }
            }
            __syncthreads();
            if (tid == 0) {
                unsigned need = (unsigned)need1, cum = 0; int bb = 0;
                for (; bb < 2047; bb++) { if (cum + hist[bb] >= need) break; cum += hist[bb]; }
                s_c = (int)((pfx11 << 11) | (unsigned)bb);
                s_cnt = 0;
            }
            __syncthreads();
            unsigned pfx22 = (unsigned)s_c;
            __syncthreads();
            for (int j = tid; j < N_PRED; j += nth) {
                float g = grow[j];
                if (!(g > IOU_THRES)) continue;
                unsigned k = ~fkey(g);
                if ((k >> 10) <= pfx22) {
                    int slot = atomicAdd(&s_cnt, 1);
                    if (slot < SEL_CAP) buf[slot] = ((ull)k << 32) | (unsigned)j;
                }
            }
            __syncthreads();
            tot = s_cnt;
        }
        int cc = (tot < SEL_CAP) ? tot : SEL_CAP;
        int n2 = 512; while (n2 < cc) n2 <<= 1;
        for (int i = tid + cc; i < n2; i += nth) buf[i] = 0xFFFFFFFFFFFFFFFFull;
        __syncthreads();
        bsort(buf, n2, tid, nth);   // key asc == giou desc, idx asc
        int cnt = (cc < GC_NEED) ? cc : GC_NEED;
        for (int i = tid; i < cnt; i += nth)
            d_gcand_idx[row][i] = (int)(buf[i] & 0xFFFFFFFFull);
        if (tid == 0) d_gcand_cnt[row] = cnt;
    }
}

// ------------------- LSA (slot-based smem state) + dynamic assign + output -----------
__global__ void k_lsa(float* __restrict__ out) {
    extern __shared__ unsigned char dsm[];
    uint16_t* shSlot = (uint16_t*)(dsm + OFF_SLOT);   // cid -> slot (0xFFFF = untouched)
    double*   sDist  = (double*)(dsm + OFF_DIST);
    uint8_t*  sPath  = (uint8_t*)(dsm + OFF_PATH);
    uint16_t* sCol   = (uint16_t*)(dsm + OFF_COL);    // slot -> cid
    unsigned* sSC    = (unsigned*)(dsm + OFF_SC);     // per-slot SC bits
    uint8_t*  shR    = (uint8_t*)(dsm + OFF_R);       // cid -> row (255 = free)
    uint16_t* vslot  = (uint16_t*)(dsm + OFF_VSLOT);  // cid -> v slot (0xFFFF = v==0)
    double*   vval   = (double*)(dsm + OFF_VVAL);
    int*      cbase  = (int*)(dsm + OFF_SLOT);        // alias during prologue only

    __shared__ double u[N_GT];
    __shared__ int SR[N_GT];
    __shared__ int c4r[N_GT];
    __shared__ int pend[N_GT];
    __shared__ int scnt[N_GT];
    __shared__ float s0val[N_GT];
    __shared__ int   s0idx[N_GT];
    __shared__ int   colro[N_GT];
    __shared__ double rv[8];
    __shared__ int rc[8];
    __shared__ int tsum[256];
    __shared__ int s_row, s_sink, s_tcnt, s_vcnt, s_npend, s_nSR;
    __shared__ double s_minval;

    int tid = threadIdx.x, nth = blockDim.x;  // 256
    const double DINF = 1e300;

    // ---- compact scan of column bitmap (cbase aliases shSlot region) ----
    int wbase = tid * 8;
    int cnts8[8]; int ssum = 0;
    #pragma unroll
    for (int w = 0; w < 8; w++) { cnts8[w] = __popc(d_colbm[wbase + w]); ssum += cnts8[w]; }
    tsum[tid] = ssum;
    __syncthreads();
    for (int off = 1; off < 256; off <<= 1) {
        int v_ = 0;
        if (tid >= off) v_ = tsum[tid - off];
        __syncthreads();
        tsum[tid] += v_;
        __syncthreads();
    }
    int excl = tsum[tid] - ssum;
    #pragma unroll
    for (int w = 0; w < 8; w++) { cbase[wbase + w] = excl; excl += cnts8[w]; }
    __syncthreads();
    int nK = tsum[255];
    if (nK > LSA_CAP) nK = LSA_CAP;   // impossible (union <= 16384), safety only

    // ---- remap: build packed (val|cid) candidates + reverse map ----
    for (int x = tid; x < N_GT * CAND_C; x += nth) {
        int row = x >> 7, s = x & 127;
        if (s < d_ccand_cnt[row]) {
            int j = d_ccand_idx[row][s];
            int w = j >> 5;
            int cid = cbase[w] + __popc(d_colbm[w] & ((1u << (j & 31)) - 1u));
            float v_ = d_ccand_val[row][s];
            d_ccpack[row][s] = ((ull)__float_as_uint(v_) << 32) | (unsigned)cid;
            d_rev[cid] = j;
        }
    }
    __syncthreads();   // cbase dead; shSlot region free

    // ---- init smem state ----
    {
        unsigned* p32 = (unsigned*)shSlot;
        for (int i = tid; i < LSA_CAP/2; i += nth) p32[i] = 0xFFFFFFFFu;
        unsigned* q32 = (unsigned*)vslot;
        for (int i = tid; i < LSA_CAP/2; i += nth) q32[i] = 0xFFFFFFFFu;
    }
    for (int i = tid; i < nK; i += nth) shR[i] = 0xFF;
    for (int i = tid; i < SLOT_CAP/32; i += nth) sSC[i] = 0;
    if (tid < N_GT) {
        c4r[tid] = -1;
        scnt[tid] = d_ccand_cnt[tid];
        ull pk = d_ccpack[tid][0];
        s0idx[tid] = (int)(pk & 0xFFFFFFFFull);
        s0val[tid] = __uint_as_float((unsigned)(pk >> 32));
    }
    if (tid == 0) s_vcnt = 0;
    __syncthreads();

    // ---- greedy tight assignment (pure smem, serial) ----
    if (tid == 0) {
        s_npend = 0;
        for (int i = 0; i < N_GT; i++) {
            if (scnt[i] > 0) {
                u[i] = (double)s0val[i];
                int j = s0idx[i];
                if (j >= 0 && j < nK && shR[j] == 0xFF) {
                    shR[j] = (uint8_t)i; c4r[i] = j;
                    continue;
                }
            } else u[i] = 0.0;
            pend[s_npend++] = i;
        }
    }
    __syncthreads();
    int npend = s_npend;

    // ---- block-wide shortest augmenting path per conflicted row ----
    for (int pi = 0; pi < npend; pi++) {
        int cur = pend[pi];
        if (tid == 0) { s_row = cur; s_sink = -1; s_tcnt = 0; s_nSR = 0; s_minval = 0.0; }
        __syncthreads();
        for (int step = 0; step < N_GT; step++) {
            int i = s_row;
            if (tid == 0) SR[s_nSR++] = i;
            double mv0 = s_minval, ui = u[i];
            int cnt = scnt[i];
            for (int s = tid; s < cnt; s += nth) {
                ull pk = d_ccpack[i][s];
                int cid = (int)(pk & 0xFFFFFFFFull);
                int slot = shSlot[cid];
                if (slot != 0xFFFF && ((sSC[slot >> 5] >> (slot & 31)) & 1u)) continue;
                int vs = vslot[cid];
                double v_ = (vs != 0xFFFF) ? vval[vs] : 0.0;
                double r = ((mv0 + (double)__uint_as_float((unsigned)(pk >> 32))) - ui) - v_;
                if (slot == 0xFFFF) {
                    int t2 = atomicAdd(&s_tcnt, 1);
                    if (t2 < SLOT_CAP) {
                        shSlot[cid] = (uint16_t)t2;
                        sCol[t2] = (uint16_t)cid;
                        sDist[t2] = r;
                        sPath[t2] = (uint8_t)i;
                    }
                } else if (r < sDist[slot]) {
                    sDist[slot] = r; sPath[slot] = (uint8_t)i;
                }
            }
            __syncthreads();
            int tcnt = s_tcnt; if (tcnt > SLOT_CAP) tcnt = SLOT_CAP;
            double bv = DINF; int bc = 0x7fffffff;
            for (int t2 = tid; t2 < tcnt; t2 += nth) {
                if ((sSC[t2 >> 5] >> (t2 & 31)) & 1u) continue;
                double sv = sDist[t2];
                int cid = sCol[t2];
                if (sv < bv || (sv == bv && cid < bc)) { bv = sv; bc = cid; }
            }
            #pragma unroll
            for (int off = 16; off > 0; off >>= 1) {
                double ov = __shfl_down_sync(0xffffffffu, bv, off);
                int   oc = __shfl_down_sync(0xffffffffu, bc, off);
                if (ov < bv || (ov == bv && oc < bc)) { bv = ov; bc = oc; }
            }
            if ((tid & 31) == 0) { rv[tid >> 5] = bv; rc[tid >> 5] = bc; }
            __syncthreads();
            if (tid == 0) {
                double fbv = rv[0]; int fbc = rc[0];
                #pragma unroll
                for (int k = 1; k < 8; k++) {
                    if (rv[k] < fbv || (rv[k] == fbv && rc[k] < fbc)) { fbv = rv[k]; fbc = rc[k]; }
                }
                if (fbc >= 0 && fbc < nK) {
                    s_minval = fbv;
                    int slot = shSlot[fbc];
                    sSC[slot >> 5] |= (1u << (slot & 31));
                    int r4 = shR[fbc];
                    if (r4 == 0xFF) s_sink = fbc; else s_row = r4;
                } else s_sink = -2;
            }
            __syncthreads();
            if (s_sink != -1) break;
        }
        if (s_sink >= 0) {
            double mv = s_minval;
            if (tid == 0) {
                u[cur] += mv;
                for (int k = 1; k < s_nSR; k++) {
                    int i2 = SR[k];
                    u[i2] += mv - sDist[shSlot[c4r[i2]]];
                }
            }
            int tcnt = s_tcnt; if (tcnt > SLOT_CAP) tcnt = SLOT_CAP;
            for (int t2 = tid; t2 < tcnt; t2 += nth) {
                if ((sSC[t2 >> 5] >> (t2 & 31)) & 1u) {
                    int cid = sCol[t2];
                    int vs = vslot[cid];
                    if (vs == 0xFFFF) {
                        vs = atomicAdd(&s_vcnt, 1);
                        if (vs < VV_CAP) { vslot[cid] = (uint16_t)vs; vval[vs] = 0.0; }
                    }
                    if (vs < VV_CAP) vval[vs] -= mv - sDist[t2];
                }
            }
            __syncthreads();
            if (tid == 0) {
                int j = s_sink;
                for (int it = 0; it <= N_GT && j >= 0; it++) {
                    int i2 = sPath[shSlot[j]];
                    shR[j] = (uint8_t)i2;
                    int tmp = c4r[i2];
                    c4r[i2] = j;
                    j = tmp;
                    if (i2 == cur) break;
                }
            }
        }
        __syncthreads();
        // reset touched state for next augmentation
        {
            unsigned* p32 = (unsigned*)shSlot;
            for (int i = tid; i < LSA_CAP/2; i += nth) p32[i] = 0xFFFFFFFFu;
            int tw = (s_tcnt < SLOT_CAP ? s_tcnt : SLOT_CAP);
            for (int i = tid; i < (tw + 31) / 32; i += nth) sSC[i] = 0;
        }
        __syncthreads();
    }
    if (tid < N_GT) colro[tid] = (c4r[tid] >= 0) ? d_rev[c4r[tid]] : -1;
    __syncthreads();

    // ================= dynamic assignment phase (reuses dead dsm region) =================
    unsigned* used = (unsigned*)dsm;                    // 8KB @ 0
    int* res_p = (int*)(dsm + 8192);                    // 5632B
    int* res_g = (int*)(dsm + 13824);                   // 5632B
    int* pref  = (int*)(dsm + 19456);                   // 16KB: pref[g*32+s], depth 32
    int* gcnts = (int*)(dsm + 35840);                   // 512B
    int* ordv  = (int*)(dsm + 36352);                   // 512B
    float* mg  = (float*)(dsm + 36864);                 // 512B

    for (int i = tid; i < NBMW; i += nth) used[i] = 0;
    if (tid < N_GT) { gcnts[tid] = d_gcand_cnt[tid]; mg[tid] = d_maxg[tid]; }
    __syncthreads();
    if (tid < N_GT) {
        float mv = mg[tid]; int r = 0;
        for (int j = 0; j < N_GT; j++) {
            float o = mg[j];
            if (o < mv || (o == mv && j < tid)) r++;
        }
        ordv[r] = tid;
    }
    for (int i = tid; i < N_GT * 32; i += nth) {
        int g = i >> 5, s = i & 31;
        pref[i] = (s < gcnts[g]) ? d_gcand_idx[g][s] : -1;
    }
    if (tid < N_GT) {
        int p = colro[tid];
        if (p >= 0 && p < N_PRED) atomicOr(&used[p >> 5], 1u << (p & 31));
        res_p[tid] = p;
        res_g[tid] = tid;
    }
    __syncthreads();
    if (tid < 32) {
        int lane = tid;
        for (int t = 0; t < N_GT; t++) {
            int g = ordv[t];
            int cnt = gcnts[g];
            int picked = 0;
            for (int base = 0; base < cnt && picked < MAX_DYN; base += 32) {
                int idx = -1;
                if (base + lane < cnt)
                    idx = (base == 0) ? pref[g * 32 + lane] : d_gcand_idx[g][base + lane];
                bool elig = (idx >= 0) && (idx < N_PRED) && !((used[idx >> 5] >> (idx & 31)) & 1u);
                unsigned m = __ballot_sync(0xffffffffu, elig);
                int K = MAX_DYN - picked;
                int pre = __popc(m & ((1u << lane) - 1u));
                if (elig && pre < K) {
                    atomicOr(&used[idx >> 5], 1u << (idx & 31));
                    res_p[128 + t * MAX_DYN + picked + pre] = idx;
                    res_g[128 + t * MAX_DYN + picked + pre] = g;
                }
                int got = __popc(m); if (got > K) got = K;
                picked += got;
                __syncwarp();
            }
            if (lane >= picked && lane < MAX_DYN) {
                res_p[128 + t * MAX_DYN + lane] = -1;
                res_g[128 + t * MAX_DYN + lane] = -1;
            }
            __syncwarp();
        }
    }
    __syncthreads();
    for (int i = tid; i < 1408; i += nth) {
        out[i]        = (float)res_p[i];
        out[1408 + i] = (float)res_g[i];
    }
}

// ------------------- launch (inputs resolved by element count) -------------------
extern "C" void kernel_launch(void* const* d_in, const int* in_sizes, int n_in,
                              void* d_out, int out_size) {
    const float* all_centers = 0;
    const float* all_sizes   = 0;
    const float* all_cls     = 0;
    const float* gt_centers  = 0;
    const float* gt_sizes    = 0;
    const void*  gt_labels   = 0;
    int seen196 = 0, seen384 = 0;
    for (int i = 0; i < n_in; i++) {
        long long s = in_sizes[i];
        if (s == (long long)N_PRED * N_CLS) {
            all_cls = (const float*)d_in[i];
        } else if (s == (long long)N_PRED * 3) {
            if (seen196++ == 0) all_centers = (const float*)d_in[i];
            else                all_sizes   = (const float*)d_in[i];
        } else if (s == (long long)N_GT * 3) {
            if (seen384++ == 0) gt_centers = (const float*)d_in[i];
            else                gt_sizes   = (const float*)d_in[i];
        } else if (s == (long long)N_GT) {
            gt_labels = d_in[i];
        }
    }

    cudaFuncSetAttribute(k_lsa, cudaFuncAttributeMaxDynamicSharedMemorySize, LSA_DYN_BYTES);

    k_cost<<<N_PRED / 128, 512>>>(all_centers, all_sizes, all_cls, gt_centers, gt_sizes, gt_labels);
    k_select<<<2 * N_GT, 512>>>();
    k_lsa<<<1, 256, LSA_DYN_BYTES>>>((float*)d_out);
}

// round 13
// speedup vs baseline: 1.2475x; 1.0105x over previous
#include <cuda_runtime.h>
#include <math.h>
#include <stdint.h>

#define N_PRED 65536
#define N_GT   128
#define N_CLS  256
#define MAX_DYN 10
#define GEPS   1e-6f
#define IOU_THRES 0.25f
#define CAND_C 128      // per-row LSA candidates: exactly the 128 smallest
#define SEL_CAP 4096    // collection buffer cap (smem)
#define GC_NEED 1408    // per-gt dynamic candidate depth (10 + 128 + 10*127)
#define NBMW   (N_PRED/32)   // 2048 bitmap words
#define LSA_CAP 16512        // compact column universe cap; union <= 16384
#define SLOT_CAP 8192        // touched-column slots per augmentation
#define VV_CAP   2048        // nonzero-dual slots (persistent)

// dynamic smem layout for k_lsa
#define OFF_SLOT   0                         // u16[LSA_CAP]          33024
#define OFF_DIST   33024                     // f64[SLOT_CAP]         65536
#define OFF_PATH   98560                     // u8[SLOT_CAP]           8192
#define OFF_COL    106752                    // u16[SLOT_CAP]         16384
#define OFF_SC     123136                    // u32[SLOT_CAP/32]       1024
#define OFF_R      124160                    // u8[LSA_CAP]           16512
#define OFF_VSLOT  140672                    // u16[LSA_CAP]          33024
#define OFF_VVAL   173696                    // f64[VV_CAP]           16384
#define LSA_DYN_BYTES 190080

// dynamic smem for k_cost: gp1(2KB) + gp2(2KB) + sig_sh 128*129*4
#define COST_DYN_BYTES (4096 + 128*129*4)   // 70144

typedef unsigned long long ull;

// ------------------- scratch (device globals; no runtime allocation) -------------------
__device__ float  d_giou[N_GT][N_PRED];   // 32MB  giou_T[g][p]
__device__ float  d_costm[N_GT][N_PRED];  // 32MB  cost_T[g][p]
__device__ float  d_maxg[N_GT];

__device__ int    d_ccand_idx[N_GT][CAND_C];  // orig col ids, sorted (cost,idx) asc
__device__ float  d_ccand_val[N_GT][CAND_C];
__device__ int    d_ccand_cnt[N_GT];
__device__ ull    d_ccpack[N_GT][CAND_C];     // (val_bits<<32)|compact_id

__device__ int    d_gcand_idx[N_GT][GC_NEED];
__device__ int    d_gcand_cnt[N_GT];

__device__ unsigned d_colbm[NBMW];
__device__ int    d_rev[N_PRED];          // compact id -> orig col

// monotonic ascending key for float
__device__ __forceinline__ unsigned fkey(float f) {
    unsigned u = __float_as_uint(f);
    return (u & 0x80000000u) ? ~u : (u | 0x80000000u);
}

// block bitonic sort, ascending, n = power of two >= blockDim
__device__ __forceinline__ void bsort(ull* a, int n, int tid, int nth) {
    for (int k = 2; k <= n; k <<= 1) {
        for (int j = k >> 1; j > 0; j >>= 1) {
            for (int i = tid; i < n; i += nth) {
                int ixj = i ^ j;
                if (ixj > i) {
                    bool up = ((i & k) == 0);
                    ull x = a[i], y = a[ixj];
                    if ((x > y) == up) { a[i] = y; a[ixj] = x; }
                }
            }
            __syncthreads();
        }
    }
}

// ------------------- cost + giou matrices (validated fp32; smem-staged sigmoids) -------
__global__ void k_cost(const float* __restrict__ pc, const float* __restrict__ ps,
                       const float* __restrict__ cls,
                       const float* __restrict__ gc, const float* __restrict__ gs,
                       const void* __restrict__ lab) {
    extern __shared__ unsigned char csm[];
    float4* gp1 = (float4*)csm;                  // lo0, lo1, lo2, gvol
    float4* gp2 = (float4*)(csm + 2048);         // hi0, hi1, hi2, (unused)
    float*  sig_sh = (float*)(csm + 4096);       // [g*129 + p_local], conflict-free
    __shared__ int glab[N_GT];
    __shared__ int is32;
    int tid = threadIdx.x;  // blockDim = 512
    if (blockIdx.x == 0) {
        for (int i = tid; i < NBMW; i += blockDim.x) d_colbm[i] = 0u;
    }
    if (tid == 0) {
        const ull* p8 = (const ull*)lab;
        int f = 0;
        for (int i = 0; i < 64; i++) { if (p8[i] >> 32) { f = 1; break; } }
        is32 = f;
    }
    __syncthreads();
    if (tid < N_GT) {
        int t = tid;
        long long lv;
        if (is32) lv = (long long)((const int*)lab)[t];
        else      lv = ((const long long*)lab)[t];
        int iv = (int)lv;
        if (iv < 0) iv = 0;
        if (iv >= N_CLS) iv = N_CLS - 1;
        glab[t] = iv;
        float c0 = gc[t*3+0], c1 = gc[t*3+1], c2 = gc[t*3+2];
        float s0 = gs[t*3+0], s1 = gs[t*3+1], s2 = gs[t*3+2];
        float h0s = __fmul_rn(s0, 0.5f), h1s = __fmul_rn(s1, 0.5f), h2s = __fmul_rn(s2, 0.5f);
        float l0 = __fsub_rn(c0, h0s), l1 = __fsub_rn(c1, h1s), l2 = __fsub_rn(c2, h2s);
        float h0 = __fadd_rn(c0, h0s), h1 = __fadd_rn(c1, h1s), h2 = __fadd_rn(c2, h2s);
        float gv = __fmul_rn(__fmul_rn(__fsub_rn(h0,l0), __fsub_rn(h1,l1)), __fsub_rn(h2,l2));
        gp1[t] = make_float4(l0, l1, l2, gv);
        gp2[t] = make_float4(h0, h1, h2, 0.0f);
    }
    __syncthreads();

    // ---- phase A: warp-cooperative sigmoid staging (gathers within one 1KB cls row) ----
    {
        int w = tid >> 5, lane = tid & 31;
        for (int pl = w; pl < 128; pl += 16) {
            const float* clsrow = cls + ((size_t)(blockIdx.x * 128 + pl)) * N_CLS;
            #pragma unroll
            for (int q = 0; q < 4; q++) {
                int g = lane + q * 32;
                float cv = __ldg(clsrow + glab[g]);
                float sig = __fdiv_rn(1.0f, __fadd_rn(1.0f, expf(-cv)));
                sig_sh[g * 129 + pl] = sig;
            }
        }
    }
    __syncthreads();

    // ---- phase B: main matrix computation ----
    int pl = tid & 127;
    int p = blockIdx.x * 128 + pl;
    int gbase = (tid >> 7) * 32;          // 4 quarters of the g-loop
    float c0 = pc[p*3+0], c1 = pc[p*3+1], c2 = pc[p*3+2];
    float s0 = ps[p*3+0], s1 = ps[p*3+1], s2 = ps[p*3+2];
    float h0s = __fmul_rn(s0, 0.5f), h1s = __fmul_rn(s1, 0.5f), h2s = __fmul_rn(s2, 0.5f);
    float pl0 = __fsub_rn(c0, h0s), pl1 = __fsub_rn(c1, h1s), pl2 = __fsub_rn(c2, h2s);
    float ph0 = __fadd_rn(c0, h0s), ph1 = __fadd_rn(c1, h1s), ph2 = __fadd_rn(c2, h2s);
    float vol1 = __fmul_rn(__fmul_rn(__fsub_rn(ph0,pl0), __fsub_rn(ph1,pl1)), __fsub_rn(ph2,pl2));

    #pragma unroll 4
    for (int gi_ = 0; gi_ < 32; gi_++) {
        int g = gbase + gi_;
        float4 A = gp1[g];
        float4 B = gp2[g];
        float d0 = fmaxf(__fsub_rn(fminf(ph0, B.x), fmaxf(pl0, A.x)), 0.f);
        float d1 = fmaxf(__fsub_rn(fminf(ph1, B.y), fmaxf(pl1, A.y)), 0.f);
        float d2 = fmaxf(__fsub_rn(fminf(ph2, B.z), fmaxf(pl2, A.z)), 0.f);
        float ov = __fmul_rn(__fmul_rn(d0, d1), d2);
        float un = fmaxf(__fsub_rn(__fadd_rn(vol1, A.w), ov), GEPS);
        float iou = __fdiv_rn(ov, un);
        float e0 = fmaxf(__fsub_rn(fmaxf(ph0, B.x), fminf(pl0, A.x)), 0.f);
        float e1 = fmaxf(__fsub_rn(fmaxf(ph1, B.y), fminf(pl1, A.y)), 0.f);
        float e2 = fmaxf(__fsub_rn(fmaxf(ph2, B.z), fminf(pl2, A.z)), 0.f);
        float enc = fmaxf(__fmul_rn(__fmul_rn(e0, e1), e2), GEPS);
        float gg = __fsub_rn(iou, __fdiv_rn(__fsub_rn(enc, un), enc));
        float sig = sig_sh[g * 129 + pl];
        d_giou[g][p] = gg;
        d_costm[g][p] = __fadd_rn(-sig, __fmul_rn(-2.0f, gg));
    }
}

// ------------------- selection: single-pass sample-threshold + sort (vectorized) -------
__global__ void k_select() {
    __shared__ ull buf[SEL_CAP];     // 32KB (aliased as hist in rare fallbacks)
    __shared__ ull samp[512];
    __shared__ float redf[512];
    __shared__ int s_cnt, s_c;

    int b = blockIdx.x, tid = threadIdx.x, nth = blockDim.x;  // nth = 512
    unsigned* hist = (unsigned*)buf;   // 2048-bin fallback histogram

    if (b < N_GT) {
        // ================= cost row =================
        int row = b;
        const float* crow = d_costm[row];
        const float4* crow4 = (const float4*)crow;
        if (tid < 512) {
            float v = crow[tid * 128];
            samp[tid] = ((ull)fkey(v) << 32) | (unsigned)(tid * 128);
        }
        __syncthreads();
        bsort(samp, 512, tid, nth);

        const int slist[5] = {4, 16, 64, 255, 511};
        int si = 0, cc = 0, truecnt = 0;
        while (true) {
            if (tid == 0) s_cnt = 0;
            __syncthreads();
            unsigned Tkey = (unsigned)(samp[slist[si]] >> 32);
            for (int j4 = tid; j4 < N_PRED / 4; j4 += nth) {
                float4 v4 = crow4[j4];
                int j = j4 * 4;
                unsigned k0 = fkey(v4.x), k1 = fkey(v4.y), k2 = fkey(v4.z), k3 = fkey(v4.w);
                if (k0 <= Tkey) { int s = atomicAdd(&s_cnt, 1); if (s < SEL_CAP) buf[s] = ((ull)k0 << 32) | (unsigned)(j+0); }
                if (k1 <= Tkey) { int s = atomicAdd(&s_cnt, 1); if (s < SEL_CAP) buf[s] = ((ull)k1 << 32) | (unsigned)(j+1); }
                if (k2 <= Tkey) { int s = atomicAdd(&s_cnt, 1); if (s < SEL_CAP) buf[s] = ((ull)k2 << 32) | (unsigned)(j+2); }
                if (k3 <= Tkey) { int s = atomicAdd(&s_cnt, 1); if (s < SEL_CAP) buf[s] = ((ull)k3 << 32) | (unsigned)(j+3); }
            }
            __syncthreads();
            truecnt = s_cnt;
            cc = (truecnt < SEL_CAP) ? truecnt : SEL_CAP;
            if (truecnt >= CAND_C && truecnt <= SEL_CAP) break;
            if (truecnt > SEL_CAP) {
                // rare: tie-heavy. exact 2-level 2048-bin histogram for the 128th key.
                for (int i = tid; i < 2048; i += nth) hist[i] = 0;
                __syncthreads();
                for (int j = tid; j < N_PRED; j += nth)
                    atomicAdd(&hist[fkey(crow[j]) >> 21], 1u);
                __syncthreads();
                if (tid == 0) {
                    unsigned need = CAND_C, cum = 0; int bb = 0;
                    for (; bb < 2047; bb++) { if (cum + hist[bb] >= need) break; cum += hist[bb]; }
                    s_c = bb; s_cnt = (int)(need - cum);
                }
                __syncthreads();
                unsigned pfx11 = (unsigned)s_c; int need1 = s_cnt;
                __syncthreads();
                for (int i = tid; i < 2048; i += nth) hist[i] = 0;
                __syncthreads();
                for (int j = tid; j < N_PRED; j += nth) {
                    unsigned k = fkey(crow[j]);
                    if ((k >> 21) == pfx11) atomicAdd(&hist[(k >> 10) & 2047u], 1u);
                }
                __syncthreads();
                if (tid == 0) {
                    unsigned need = (unsigned)need1, cum = 0; int bb = 0;
                    for (; bb < 2047; bb++) { if (cum + hist[bb] >= need) break; cum += hist[bb]; }
                    s_c = (int)((pfx11 << 11) | (unsigned)bb);
                    s_cnt = 0;
                }
                __syncthreads();
                unsigned pfx22 = (unsigned)s_c;
                __syncthreads();
                for (int j = tid; j < N_PRED; j += nth) {
                    unsigned k = fkey(crow[j]);
                    if ((k >> 10) <= pfx22) {
                        int slot = atomicAdd(&s_cnt, 1);
                        if (slot < SEL_CAP) buf[slot] = ((ull)k << 32) | (unsigned)j;
                    }
                }
                __syncthreads();
                truecnt = s_cnt;
                cc = (truecnt < SEL_CAP) ? truecnt : SEL_CAP;
                break;
            }
            si++;
            if (si >= 5) break;
            __syncthreads();
        }
        int n2 = 512; while (n2 < cc) n2 <<= 1;
        for (int i = tid + cc; i < n2; i += nth) buf[i] = 0xFFFFFFFFFFFFFFFFull;
        __syncthreads();
        bsort(buf, n2, tid, nth);
        int keep = (cc < CAND_C) ? cc : CAND_C;
        for (int i = tid; i < keep; i += nth) {
            ull e = buf[i];
            int j = (int)(e & 0xFFFFFFFFull);
            d_ccand_idx[row][i] = j;
            d_ccand_val[row][i] = crow[j];
            atomicOr(&d_colbm[j >> 5], 1u << (j & 31));
        }
        if (tid == 0) d_ccand_cnt[row] = keep;
    } else {
        // ================= giou row: fused max + collect (vectorized) =================
        int row = b - N_GT;
        const float* grow = d_giou[row];
        const float4* grow4 = (const float4*)grow;
        if (tid == 0) s_cnt = 0;
        __syncthreads();
        float lmax = -1e30f;
        for (int j4 = tid; j4 < N_PRED / 4; j4 += nth) {
            float4 g4 = grow4[j4];
            int j = j4 * 4;
            lmax = fmaxf(lmax, fmaxf(fmaxf(g4.x, g4.y), fmaxf(g4.z, g4.w)));
            if (g4.x > IOU_THRES) { int s = atomicAdd(&s_cnt, 1); if (s < SEL_CAP) buf[s] = ((ull)(~fkey(g4.x)) << 32) | (unsigned)(j+0); }
            if (g4.y > IOU_THRES) { int s = atomicAdd(&s_cnt, 1); if (s < SEL_CAP) buf[s] = ((ull)(~fkey(g4.y)) << 32) | (unsigned)(j+1); }
            if (g4.z > IOU_THRES) { int s = atomicAdd(&s_cnt, 1); if (s < SEL_CAP) buf[s] = ((ull)(~fkey(g4.z)) << 32) | (unsigned)(j+2); }
            if (g4.w > IOU_THRES) { int s = atomicAdd(&s_cnt, 1); if (s < SEL_CAP) buf[s] = ((ull)(~fkey(g4.w)) << 32) | (unsigned)(j+3); }
        }
        redf[tid] = lmax;
        __syncthreads();
        for (int off = nth >> 1; off > 0; off >>= 1) {
            if (tid < off) redf[tid] = fmaxf(redf[tid], redf[tid + off]);
            __syncthreads();
        }
        if (tid == 0) d_maxg[row] = redf[0];
        int tot = s_cnt;
        __syncthreads();
        if (tot > SEL_CAP) {
            // rare overflow: 2-level histogram over qualifiers, then bounded re-collect
            for (int i = tid; i < 2048; i += nth) hist[i] = 0;
            __syncthreads();
            for (int j = tid; j < N_PRED; j += nth) {
                float g = grow[j];
                if (g > IOU_THRES) atomicAdd(&hist[(~fkey(g)) >> 21], 1u);
            }
            __syncthreads();
            if (tid == 0) {
                unsigned need = GC_NEED, cum = 0; int bb = 0;
                for (; bb < 2047; bb++) { if (cum + hist[bb] >= need) break; cum += hist[bb]; }
                s_c = bb; s_cnt = (int)(need - cum);
            }
            __syncthreads();
            unsigned pfx11 = (unsigned)s_c; int need1 = s_cnt;
            __syncthreads();
            for (int i = tid; i < 2048; i += nth) hist[i] = 0;
            __syncthreads();
            for (int j = tid; j < N_PRED; j += nth) {
                float g = grow[j];
                if (g > IOU_THRES) {
                    unsigned k = ~fkey(g);
                    if ((k >> 21) == pfx11) atomicAdd(&hist[(k >> 10) & 2047u], 1u);
                }
            }
            __syncthreads();
            if (tid == 0) {
                unsigned need = (unsigned)need1, cum = 0; int bb = 0;
                for (; bb < 2047; bb++) { if (cum + hist[bb] >= need) break; cum += hist[bb]; }
                s_c = (int)((pfx11 << 11) | (unsigned)bb);
                s_cnt = 0;
            }
            __syncthreads();
            unsigned pfx22 = (unsigned)s_c;
            __syncthreads();
            for (int j = tid; j < N_PRED; j += nth) {
                float g = grow[j];
                if (!(g > IOU_THRES)) continue;
                unsigned k = ~fkey(g);
                if ((k >> 10) <= pfx22) {
                    int slot = atomicAdd(&s_cnt, 1);
                    if (slot < SEL_CAP) buf[slot] = ((ull)k << 32) | (unsigned)j;
                }
            }
            __syncthreads();
            tot = s_cnt;
        }
        int cc = (tot < SEL_CAP) ? tot : SEL_CAP;
        int n2 = 512; while (n2 < cc) n2 <<= 1;
        for (int i = tid + cc; i < n2; i += nth) buf[i] = 0xFFFFFFFFFFFFFFFFull;
        __syncthreads();
        bsort(buf, n2, tid, nth);   // key asc == giou desc, idx asc
        int cnt = (cc < GC_NEED) ? cc : GC_NEED;
        for (int i = tid; i < cnt; i += nth)
            d_gcand_idx[row][i] = (int)(buf[i] & 0xFFFFFFFFull);
        if (tid == 0) d_gcand_cnt[row] = cnt;
    }
}

// ------------------- LSA (slot-based smem state) + dynamic assign + output -----------
__global__ void k_lsa(float* __restrict__ out) {
    extern __shared__ unsigned char dsm[];
    uint16_t* shSlot = (uint16_t*)(dsm + OFF_SLOT);   // cid -> slot (0xFFFF = untouched)
    double*   sDist  = (double*)(dsm + OFF_DIST);
    uint8_t*  sPath  = (uint8_t*)(dsm + OFF_PATH);
    uint16_t* sCol   = (uint16_t*)(dsm + OFF_COL);    // slot -> cid
    unsigned* sSC    = (unsigned*)(dsm + OFF_SC);     // per-slot SC bits
    uint8_t*  shR    = (uint8_t*)(dsm + OFF_R);       // cid -> row (255 = free)
    uint16_t* vslot  = (uint16_t*)(dsm + OFF_VSLOT);  // cid -> v slot (0xFFFF = v==0)
    double*   vval   = (double*)(dsm + OFF_VVAL);
    int*      cbase  = (int*)(dsm + OFF_SLOT);        // alias during prologue only

    __shared__ double u[N_GT];
    __shared__ int SR[N_GT];
    __shared__ int c4r[N_GT];
    __shared__ int pend[N_GT];
    __shared__ int scnt[N_GT];
    __shared__ float s0val[N_GT];
    __shared__ int   s0idx[N_GT];
    __shared__ int   colro[N_GT];
    __shared__ double rv[8];
    __shared__ int rc[8];
    __shared__ int tsum[256];
    __shared__ int s_row, s_sink, s_tcnt, s_vcnt, s_npend, s_nSR;
    __shared__ double s_minval;

    int tid = threadIdx.x, nth = blockDim.x;  // 256
    const double DINF = 1e300;

    // ---- compact scan of column bitmap (cbase aliases shSlot region) ----
    int wbase = tid * 8;
    int cnts8[8]; int ssum = 0;
    #pragma unroll
    for (int w = 0; w < 8; w++) { cnts8[w] = __popc(d_colbm[wbase + w]); ssum += cnts8[w]; }
    tsum[tid] = ssum;
    __syncthreads();
    for (int off = 1; off < 256; off <<= 1) {
        int v_ = 0;
        if (tid >= off) v_ = tsum[tid - off];
        __syncthreads();
        tsum[tid] += v_;
        __syncthreads();
    }
    int excl = tsum[tid] - ssum;
    #pragma unroll
    for (int w = 0; w < 8; w++) { cbase[wbase + w] = excl; excl += cnts8[w]; }
    __syncthreads();
    int nK = tsum[255];
    if (nK > LSA_CAP) nK = LSA_CAP;   // impossible (union <= 16384), safety only

    // ---- remap: build packed (val|cid) candidates + reverse map ----
    for (int x = tid; x < N_GT * CAND_C; x += nth) {
        int row = x >> 7, s = x & 127;
        if (s < d_ccand_cnt[row]) {
            int j = d_ccand_idx[row][s];
            int w = j >> 5;
            int cid = cbase[w] + __popc(d_colbm[w] & ((1u << (j & 31)) - 1u));
            float v_ = d_ccand_val[row][s];
            d_ccpack[row][s] = ((ull)__float_as_uint(v_) << 32) | (unsigned)cid;
            d_rev[cid] = j;
        }
    }
    __syncthreads();   // cbase dead; shSlot region free

    // ---- init smem state ----
    {
        unsigned* p32 = (unsigned*)shSlot;
        for (int i = tid; i < LSA_CAP/2; i += nth) p32[i] = 0xFFFFFFFFu;
        unsigned* q32 = (unsigned*)vslot;
        for (int i = tid; i < LSA_CAP/2; i += nth) q32[i] = 0xFFFFFFFFu;
    }
    for (int i = tid; i < nK; i += nth) shR[i] = 0xFF;
    for (int i = tid; i < SLOT_CAP/32; i += nth) sSC[i] = 0;
    if (tid < N_GT) {
        c4r[tid] = -1;
        scnt[tid] = d_ccand_cnt[tid];
        ull pk = d_ccpack[tid][0];
        s0idx[tid] = (int)(pk & 0xFFFFFFFFull);
        s0val[tid] = __uint_as_float((unsigned)(pk >> 32));
    }
    if (tid == 0) s_vcnt = 0;
    __syncthreads();

    // ---- greedy tight assignment (pure smem, serial) ----
    if (tid == 0) {
        s_npend = 0;
        for (int i = 0; i < N_GT; i++) {
            if (scnt[i] > 0) {
                u[i] = (double)s0val[i];
                int j = s0idx[i];
                if (j >= 0 && j < nK && shR[j] == 0xFF) {
                    shR[j] = (uint8_t)i; c4r[i] = j;
                    continue;
                }
            } else u[i] = 0.0;
            pend[s_npend++] = i;
        }
    }
    __syncthreads();
    int npend = s_npend;

    // ---- block-wide shortest augmenting path per conflicted row ----
    for (int pi = 0; pi < npend; pi++) {
        int cur = pend[pi];
        if (tid == 0) { s_row = cur; s_sink = -1; s_tcnt = 0; s_nSR = 0; s_minval = 0.0; }
        __syncthreads();
        for (int step = 0; step < N_GT; step++) {
            int i = s_row;
            if (tid == 0) SR[s_nSR++] = i;
            double mv0 = s_minval, ui = u[i];
            int cnt = scnt[i];
            for (int s = tid; s < cnt; s += nth) {
                ull pk = d_ccpack[i][s];
                int cid = (int)(pk & 0xFFFFFFFFull);
                int slot = shSlot[cid];
                if (slot != 0xFFFF && ((sSC[slot >> 5] >> (slot & 31)) & 1u)) continue;
                int vs = vslot[cid];
                double v_ = (vs != 0xFFFF) ? vval[vs] : 0.0;
                double r = ((mv0 + (double)__uint_as_float((unsigned)(pk >> 32))) - ui) - v_;
                if (slot == 0xFFFF) {
                    int t2 = atomicAdd(&s_tcnt, 1);
                    if (t2 < SLOT_CAP) {
                        shSlot[cid] = (uint16_t)t2;
                        sCol[t2] = (uint16_t)cid;
                        sDist[t2] = r;
                        sPath[t2] = (uint8_t)i;
                    }
                } else if (r < sDist[slot]) {
                    sDist[slot] = r; sPath[slot] = (uint8_t)i;
                }
            }
            __syncthreads();
            int tcnt = s_tcnt; if (tcnt > SLOT_CAP) tcnt = SLOT_CAP;
            double bv = DINF; int bc = 0x7fffffff;
            for (int t2 = tid; t2 < tcnt; t2 += nth) {
                if ((sSC[t2 >> 5] >> (t2 & 31)) & 1u) continue;
                double sv = sDist[t2];
                int cid = sCol[t2];
                if (sv < bv || (sv == bv && cid < bc)) { bv = sv; bc = cid; }
            }
            #pragma unroll
            for (int off = 16; off > 0; off >>= 1) {
                double ov = __shfl_down_sync(0xffffffffu, bv, off);
                int   oc = __shfl_down_sync(0xffffffffu, bc, off);
                if (ov < bv || (ov == bv && oc < bc)) { bv = ov; bc = oc; }
            }
            if ((tid & 31) == 0) { rv[tid >> 5] = bv; rc[tid >> 5] = bc; }
            __syncthreads();
            if (tid == 0) {
                double fbv = rv[0]; int fbc = rc[0];
                #pragma unroll
                for (int k = 1; k < 8; k++) {
                    if (rv[k] < fbv || (rv[k] == fbv && rc[k] < fbc)) { fbv = rv[k]; fbc = rc[k]; }
                }
                if (fbc >= 0 && fbc < nK) {
                    s_minval = fbv;
                    int slot = shSlot[fbc];
                    sSC[slot >> 5] |= (1u << (slot & 31));
                    int r4 = shR[fbc];
                    if (r4 == 0xFF) s_sink = fbc; else s_row = r4;
                } else s_sink = -2;
            }
            __syncthreads();
            if (s_sink != -1) break;
        }
        if (s_sink >= 0) {
            double mv = s_minval;
            if (tid == 0) {
                u[cur] += mv;
                for (int k = 1; k < s_nSR; k++) {
                    int i2 = SR[k];
                    u[i2] += mv - sDist[shSlot[c4r[i2]]];
                }
            }
            int tcnt = s_tcnt; if (tcnt > SLOT_CAP) tcnt = SLOT_CAP;
            for (int t2 = tid; t2 < tcnt; t2 += nth) {
                if ((sSC[t2 >> 5] >> (t2 & 31)) & 1u) {
                    int cid = sCol[t2];
                    int vs = vslot[cid];
                    if (vs == 0xFFFF) {
                        vs = atomicAdd(&s_vcnt, 1);
                        if (vs < VV_CAP) { vslot[cid] = (uint16_t)vs; vval[vs] = 0.0; }
                    }
                    if (vs < VV_CAP) vval[vs] -= mv - sDist[t2];
                }
            }
            __syncthreads();
            if (tid == 0) {
                int j = s_sink;
                for (int it = 0; it <= N_GT && j >= 0; it++) {
                    int i2 = sPath[shSlot[j]];
                    shR[j] = (uint8_t)i2;
                    int tmp = c4r[i2];
                    c4r[i2] = j;
                    j = tmp;
                    if (i2 == cur) break;
                }
            }
        }
        __syncthreads();
        // reset touched state for next augmentation
        {
            unsigned* p32 = (unsigned*)shSlot;
            for (int i = tid; i < LSA_CAP/2; i += nth) p32[i] = 0xFFFFFFFFu;
            int tw = (s_tcnt < SLOT_CAP ? s_tcnt : SLOT_CAP);
            for (int i = tid; i < (tw + 31) / 32; i += nth) sSC[i] = 0;
        }
        __syncthreads();
    }
    if (tid < N_GT) colro[tid] = (c4r[tid] >= 0) ? d_rev[c4r[tid]] : -1;
    __syncthreads();

    // ================= dynamic assignment phase (reuses dead dsm region) =================
    unsigned* used = (unsigned*)dsm;                    // 8KB @ 0
    int* res_p = (int*)(dsm + 8192);                    // 5632B
    int* res_g = (int*)(dsm + 13824);                   // 5632B
    int* pref  = (int*)(dsm + 19456);                   // 16KB: pref[g*32+s], depth 32
    int* gcnts = (int*)(dsm + 35840);                   // 512B
    int* ordv  = (int*)(dsm + 36352);                   // 512B
    float* mg  = (float*)(dsm + 36864);                 // 512B

    for (int i = tid; i < NBMW; i += nth) used[i] = 0;
    if (tid < N_GT) { gcnts[tid] = d_gcand_cnt[tid]; mg[tid] = d_maxg[tid]; }
    __syncthreads();
    if (tid < N_GT) {
        float mv = mg[tid]; int r = 0;
        for (int j = 0; j < N_GT; j++) {
            float o = mg[j];
            if (o < mv || (o == mv && j < tid)) r++;
        }
        ordv[r] = tid;
    }
    for (int i = tid; i < N_GT * 32; i += nth) {
        int g = i >> 5, s = i & 31;
        pref[i] = (s < gcnts[g]) ? d_gcand_idx[g][s] : -1;
    }
    if (tid < N_GT) {
        int p = colro[tid];
        if (p >= 0 && p < N_PRED) atomicOr(&used[p >> 5], 1u << (p & 31));
        res_p[tid] = p;
        res_g[tid] = tid;
    }
    __syncthreads();
    if (tid < 32) {
        int lane = tid;
        for (int t = 0; t < N_GT; t++) {
            int g = ordv[t];
            int cnt = gcnts[g];
            int picked = 0;
            for (int base = 0; base < cnt && picked < MAX_DYN; base += 32) {
                int idx = -1;
                if (base + lane < cnt)
                    idx = (base == 0) ? pref[g * 32 + lane] : d_gcand_idx[g][base + lane];
                bool elig = (idx >= 0) && (idx < N_PRED) && !((used[idx >> 5] >> (idx & 31)) & 1u);
                unsigned m = __ballot_sync(0xffffffffu, elig);
                int K = MAX_DYN - picked;
                int pre = __popc(m & ((1u << lane) - 1u));
                if (elig && pre < K) {
                    atomicOr(&used[idx >> 5], 1u << (idx & 31));
                    res_p[128 + t * MAX_DYN + picked + pre] = idx;
                    res_g[128 + t * MAX_DYN + picked + pre] = g;
                }
                int got = __popc(m); if (got > K) got = K;
                picked += got;
                __syncwarp();
            }
            if (lane >= picked && lane < MAX_DYN) {
                res_p[128 + t * MAX_DYN + lane] = -1;
                res_g[128 + t * MAX_DYN + lane] = -1;
            }
            __syncwarp();
        }
    }
    __syncthreads();
    for (int i = tid; i < 1408; i += nth) {
        out[i]        = (float)res_p[i];
        out[1408 + i] = (float)res_g[i];
    }
}

// ------------------- launch (inputs resolved by element count) -------------------
extern "C" void kernel_launch(void* const* d_in, const int* in_sizes, int n_in,
                              void* d_out, int out_size) {
    const float* all_centers = 0;
    const float* all_sizes   = 0;
    const float* all_cls     = 0;
    const float* gt_centers  = 0;
    const float* gt_sizes    = 0;
    const void*  gt_labels   = 0;
    int seen196 = 0, seen384 = 0;
    for (int i = 0; i < n_in; i++) {
        long long s = in_sizes[i];
        if (s == (long long)N_PRED * N_CLS) {
            all_cls = (const float*)d_in[i];
        } else if (s == (long long)N_PRED * 3) {
            if (seen196++ == 0) all_centers = (const float*)d_in[i];
            else                all_sizes   = (const float*)d_in[i];
        } else if (s == (long long)N_GT * 3) {
            if (seen384++ == 0) gt_centers = (const float*)d_in[i];
            else                gt_sizes   = (const float*)d_in[i];
        } else if (s == (long long)N_GT) {
            gt_labels = d_in[i];
        }
    }

    cudaFuncSetAttribute(k_cost, cudaFuncAttributeMaxDynamicSharedMemorySize, COST_DYN_BYTES);
    cudaFuncSetAttribute(k_lsa, cudaFuncAttributeMaxDynamicSharedMemorySize, LSA_DYN_BYTES);

    k_cost<<<N_PRED / 128, 512, COST_DYN_BYTES>>>(all_centers, all_sizes, all_cls,
                                                  gt_centers, gt_sizes, gt_labels);
    k_select<<<2 * N_GT, 512>>>();
    k_lsa<<<1, 256, LSA_DYN_BYTES>>>((float*)d_out);
}